// round 9
// baseline (speedup 1.0000x reference)
#include <cuda_runtime.h>
#include <cuda_bf16.h>
#include <cstdint>

#define N_NODES 50000
#define N_EDGES 600000
#define NFEAT 128
#define NGRAPH 64
#define POOL_ROWS 256
#define SCAN_ITEMS 49

#define STAGE_BYTES 49152  // Ah 8K | Al 8K | Bh 16K | Bl 16K
#define GEMM_SMEM (2 * STAGE_BYTES)

// ---------------- device scratch ----------------
__device__ int g_deg[N_NODES];            // zero-init; re-zeroed by k_scan
__device__ int g_off[N_NODES + 1];
__device__ int g_pos[N_NODES];
__device__ int g_src[N_EDGES];
__device__ unsigned g_pool[NGRAPH * NFEAT];  // zero-init; re-zeroed by k_fc
__device__ float g_hf0[(size_t)N_NODES * NFEAT];
__device__ float g_hf1[(size_t)N_NODES * NFEAT];
// bf16 hi/lo operand buffers: [node][128] bf16 = 256B/row
__device__ uint4 g_mh4[(size_t)N_NODES * NFEAT / 8];
__device__ uint4 g_ml4[(size_t)N_NODES * NFEAT / 8];
__device__ uint4 g_x0h4[(size_t)N_NODES * NFEAT / 8];
__device__ uint4 g_x0l4[(size_t)N_NODES * NFEAT / 8];
__device__ uint4 g_x1h4[(size_t)N_NODES * NFEAT / 8];
__device__ uint4 g_x1l4[(size_t)N_NODES * NFEAT / 8];
// W split: [3 layers][128 n][256 k] bf16 = 512B/row
__device__ uint4 g_Whi4[3 * 128 * 256 / 8];
__device__ uint4 g_Wlo4[3 * 128 * 256 / 8];

// ---------------- helpers ----------------
__device__ __forceinline__ float lrelu(float v) { return fmaxf(v, 0.01f * v); }
__device__ __forceinline__ unsigned fenc(float f) {
    unsigned u = __float_as_uint(f);
    return (u & 0x80000000u) ? ~u : (u | 0x80000000u);
}
__device__ __forceinline__ float fdec(unsigned u) {
    return (u & 0x80000000u) ? __uint_as_float(u & 0x7FFFFFFFu) : __uint_as_float(~u);
}
__device__ __forceinline__ uint32_t pack_hi(float a, float b) {
    __nv_bfloat162 p(__float2bfloat16_rn(a), __float2bfloat16_rn(b));
    return *reinterpret_cast<uint32_t*>(&p);
}
__device__ __forceinline__ uint32_t pack_lo(float a, float b) {
    float ra = a - __bfloat162float(__float2bfloat16_rn(a));
    float rb = b - __bfloat162float(__float2bfloat16_rn(b));
    __nv_bfloat162 p(__float2bfloat16_rn(ra), __float2bfloat16_rn(rb));
    return *reinterpret_cast<uint32_t*>(&p);
}
__device__ __forceinline__ uint32_t smem_u32(const void* p) {
    uint32_t a;
    asm("{ .reg .u64 t; cvta.to.shared.u64 t, %1; cvt.u32.u64 %0, t; }" : "=r"(a) : "l"(p));
    return a;
}
__device__ __forceinline__ void mma_bf16(float* c, const uint32_t* a, uint32_t b0,
                                         uint32_t b1) {
    asm volatile(
        "mma.sync.aligned.m16n8k16.row.col.f32.bf16.bf16.f32 "
        "{%0,%1,%2,%3}, {%4,%5,%6,%7}, {%8,%9}, {%0,%1,%2,%3};"
        : "+f"(c[0]), "+f"(c[1]), "+f"(c[2]), "+f"(c[3])
        : "r"(a[0]), "r"(a[1]), "r"(a[2]), "r"(a[3]), "r"(b0), "r"(b1));
}
__device__ __forceinline__ void ldsm4(uint32_t* r, uint32_t addr) {
    asm volatile("ldmatrix.sync.aligned.m8n8.x4.shared.b16 {%0,%1,%2,%3}, [%4];"
                 : "=r"(r[0]), "=r"(r[1]), "=r"(r[2]), "=r"(r[3]) : "r"(addr));
}
__device__ __forceinline__ void cp16(uint32_t dst, const void* src, int sz) {
    asm volatile("cp.async.ca.shared.global [%0], [%1], 16, %2;"
                 :: "r"(dst), "l"(src), "r"(sz));
}

// ---------------- fused: W pre-convert + degree histogram ----------------
// grid covers max(3*128*256 wconv elems, N_EDGES/4 hist threads) = 150016 threads
__global__ void k_whist(const float* __restrict__ W1l, const float* __restrict__ W1r,
                        const float* __restrict__ W2l, const float* __restrict__ W2r,
                        const float* __restrict__ W3l, const float* __restrict__ W3r,
                        const int* __restrict__ ei) {
    int i = blockIdx.x * blockDim.x + threadIdx.x;
    if (i < 3 * 128 * 256) {
        int l = i >> 15;
        int rem = i & 32767;
        int n = rem >> 8;
        int k = rem & 255;
        const float* Wl = (l == 0) ? W1l : (l == 1) ? W2l : W3l;
        const float* Wr = (l == 0) ? W1r : (l == 1) ? W2r : W3r;
        float w = (k < 128) ? Wl[k * 128 + n] : Wr[(k - 128) * 128 + n];
        __nv_bfloat16 h = __float2bfloat16_rn(w);
        ((__nv_bfloat16*)g_Whi4)[i] = h;
        ((__nv_bfloat16*)g_Wlo4)[i] = __float2bfloat16_rn(w - __bfloat162float(h));
    }
    int e4 = i * 4;
    if (e4 < N_EDGES) {
        int4 d = *(const int4*)(ei + N_EDGES + e4);
        atomicAdd(&g_deg[d.x], 1);
        atomicAdd(&g_deg[d.y], 1);
        atomicAdd(&g_deg[d.z], 1);
        atomicAdd(&g_deg[d.w], 1);
    }
}

// single-block scan; consumes g_deg and re-zeroes it for the next replay
__global__ void k_scan() {
    __shared__ int s[1024];
    int t = threadIdx.x;
    int base = t * SCAN_ITEMS;
    int sum = 0;
    for (int j = 0; j < SCAN_ITEMS; j++) {
        int i = base + j;
        if (i < N_NODES) sum += g_deg[i];
    }
    s[t] = sum;
    for (int off = 1; off < 1024; off <<= 1) {
        __syncthreads();
        int v = (t >= off) ? s[t - off] : 0;
        __syncthreads();
        s[t] += v;
    }
    __syncthreads();
    int run = s[t] - sum;
    for (int j = 0; j < SCAN_ITEMS; j++) {
        int i = base + j;
        if (i < N_NODES) {
            int d = g_deg[i];
            g_off[i] = run;
            g_pos[i] = run;
            run += d;
            g_deg[i] = 0;  // restore invariant for next launch
        }
    }
    if (t == 1023) g_off[N_NODES] = N_EDGES;
}

__global__ void k_scatter(const int* __restrict__ ei) {
    int e4 = (blockIdx.x * blockDim.x + threadIdx.x) * 4;
    if (e4 >= N_EDGES) return;
    int4 d = *(const int4*)(ei + N_EDGES + e4);
    int4 s = *(const int4*)(ei + e4);
    int p0 = atomicAdd(&g_pos[d.x], 1);
    int p1 = atomicAdd(&g_pos[d.y], 1);
    int p2 = atomicAdd(&g_pos[d.z], 1);
    int p3 = atomicAdd(&g_pos[d.w], 1);
    g_src[p0] = s.x;
    g_src[p1] = s.y;
    g_src[p2] = s.z;
    g_src[p3] = s.w;
}

// ---------------- mean-aggregation: one warp per node; 4-way unrolled --------------
__global__ __launch_bounds__(256) void k_agg(const float* __restrict__ in,
                                             uint2* __restrict__ mh, uint2* __restrict__ ml,
                                             uint2* __restrict__ xh, uint2* __restrict__ xl) {
    int node = (blockIdx.x * blockDim.x + threadIdx.x) >> 5;
    if (node >= N_NODES) return;
    int lane = threadIdx.x & 31;
    // self feature -> x-side bf16 hi/lo
    float4 sv = ((const float4*)(in + (size_t)node * NFEAT))[lane];
    xh[node * 32 + lane] = make_uint2(pack_hi(sv.x, sv.y), pack_hi(sv.z, sv.w));
    xl[node * 32 + lane] = make_uint2(pack_lo(sv.x, sv.y), pack_lo(sv.z, sv.w));
    // neighbor mean
    int s0 = g_off[node], s1 = g_off[node + 1];
    float ax = 0.f, ay = 0.f, az = 0.f, aw = 0.f;
    int e = s0;
    for (; e + 3 < s1; e += 4) {
        int sA = g_src[e], sB = g_src[e + 1], sC = g_src[e + 2], sD = g_src[e + 3];
        float4 v0 = ((const float4*)(in + (size_t)sA * NFEAT))[lane];
        float4 v1 = ((const float4*)(in + (size_t)sB * NFEAT))[lane];
        float4 v2 = ((const float4*)(in + (size_t)sC * NFEAT))[lane];
        float4 v3 = ((const float4*)(in + (size_t)sD * NFEAT))[lane];
        ax += (v0.x + v1.x) + (v2.x + v3.x);
        ay += (v0.y + v1.y) + (v2.y + v3.y);
        az += (v0.z + v1.z) + (v2.z + v3.z);
        aw += (v0.w + v1.w) + (v2.w + v3.w);
    }
    for (; e < s1; ++e) {
        float4 v = ((const float4*)(in + (size_t)g_src[e] * NFEAT))[lane];
        ax += v.x; ay += v.y; az += v.z; aw += v.w;
    }
    float inv = 1.0f / (float)max(s1 - s0, 1);
    ax *= inv; ay *= inv; az *= inv; aw *= inv;
    mh[node * 32 + lane] = make_uint2(pack_hi(ax, ay), pack_hi(az, aw));
    ml[node * 32 + lane] = make_uint2(pack_lo(ax, ay), pack_lo(az, aw));
}

// ---------------- mma.sync dual GEMM, double-buffered, 2 CTA/SM ---------------------
// Tile: 64m x 128n x 256k; 4 k-chunks of 64; 8 warps = 4m x 2n (warp 16m x 64n).
// Stage (48KB): Ah@0 (8K), Al@8K, Bh@16K (16K), Bl@32K; rows x 128B, swizzled.
__global__ __launch_bounds__(256, 2) void k_gemm(
    const uint4* __restrict__ Amh, const uint4* __restrict__ Aml,
    const uint4* __restrict__ Axh, const uint4* __restrict__ Axl,
    const uint4* __restrict__ Bh, const uint4* __restrict__ Bl,
    const float* __restrict__ bias, float* __restrict__ outf) {
    extern __shared__ char smc[];
    uint32_t sb = smem_u32(smc);
    int t = threadIdx.x, lane = t & 31, wid = t >> 5;
    int qr = lane >> 2, qc = lane & 3;
    int row0 = blockIdx.x * 64;
    int wrow = (wid & 3) * 16, wcol = (wid >> 2) * 64;

    float acc[4][2][4];
#pragma unroll
    for (int a = 0; a < 4; a++)
#pragma unroll
        for (int b = 0; b < 2; b++)
#pragma unroll
            for (int d = 0; d < 4; d++) acc[a][b][d] = 0.f;

#define STAGE(CH, BF)                                                               \
    {                                                                               \
        const int _ch = (CH);                                                       \
        uint32_t sbase = sb + (BF) * STAGE_BYTES;                                   \
        const char* abh = (const char*)(_ch < 2 ? Amh : Axh);                       \
        const char* abl = (const char*)(_ch < 2 ? Aml : Axl);                       \
        int kof = (_ch & 1) * 128, bkof = _ch * 128;                                \
        for (int g = t; g < 1024; g += 256) {                                       \
            int hi = g < 512;                                                       \
            int idx = g & 511, row = idx >> 3, c16 = idx & 7;                       \
            uint32_t dst = sbase + (hi ? 0 : 8192) + row * 128 +                    \
                           ((c16 ^ (row & 7)) * 16);                                \
            int grow = row0 + row;                                                  \
            const char* src = (hi ? abh : abl) + (size_t)grow * 256 + kof +         \
                              c16 * 16;                                             \
            cp16(dst, src, grow < N_NODES ? 16 : 0);                                \
        }                                                                           \
        for (int g = t; g < 2048; g += 256) {                                       \
            int hi = g < 1024;                                                      \
            int idx = g & 1023, row = idx >> 3, c16 = idx & 7;                      \
            uint32_t dst = sbase + 16384 + (hi ? 0 : 16384) + row * 128 +           \
                           ((c16 ^ (row & 7)) * 16);                                \
            const char* src = (hi ? (const char*)Bh : (const char*)Bl) +            \
                              row * 512 + bkof + c16 * 16;                          \
            cp16(dst, src, 16);                                                     \
        }                                                                           \
        asm volatile("cp.async.commit_group;");                                     \
    }

    STAGE(0, 0);
    for (int ch = 0; ch < 4; ch++) {
        if (ch < 3) {
            STAGE(ch + 1, (ch + 1) & 1);
            asm volatile("cp.async.wait_group 1;");
        } else {
            asm volatile("cp.async.wait_group 0;");
        }
        __syncthreads();
        uint32_t base = sb + (ch & 1) * STAGE_BYTES;
#pragma unroll
        for (int ks = 0; ks < 4; ks++) {
            uint32_t ah[4], al[4];
            {
                int row = wrow + (lane & 15);
                int c16 = ks * 2 + (lane >> 4);
                uint32_t ad = base + row * 128 + ((c16 ^ (row & 7)) * 16);
                ldsm4(ah, ad);
                ldsm4(al, ad + 8192);
            }
#pragma unroll
            for (int ni2 = 0; ni2 < 4; ni2++) {
                int row = wcol + ni2 * 16 + (lane & 7) + ((lane >> 4) << 3);
                int c16 = ks * 2 + ((lane >> 3) & 1);
                uint32_t bd = base + 16384 + row * 128 + ((c16 ^ (row & 7)) * 16);
                uint32_t bh[4], bl[4];
                ldsm4(bh, bd);
                ldsm4(bl, bd + 16384);
                mma_bf16(acc[ni2][0], ah, bh[0], bh[1]);
                mma_bf16(acc[ni2][0], ah, bl[0], bl[1]);
                mma_bf16(acc[ni2][0], al, bh[0], bh[1]);
                mma_bf16(acc[ni2][1], ah, bh[2], bh[3]);
                mma_bf16(acc[ni2][1], ah, bl[2], bl[3]);
                mma_bf16(acc[ni2][1], al, bh[2], bh[3]);
            }
        }
        __syncthreads();
    }
#undef STAGE

    // epilogue: bias + leaky_relu, fp32
#pragma unroll
    for (int ni2 = 0; ni2 < 4; ni2++)
#pragma unroll
        for (int n8 = 0; n8 < 2; n8++) {
            int col = wcol + ni2 * 16 + n8 * 8 + qc * 2;
            float b0 = __ldg(bias + col), b1 = __ldg(bias + col + 1);
            float* a = acc[ni2][n8];
            int r = row0 + wrow + qr;
            if (r < N_NODES)
                *(float2*)(outf + (size_t)r * NFEAT + col) =
                    make_float2(lrelu(a[0] + b0), lrelu(a[1] + b1));
            if (r + 8 < N_NODES)
                *(float2*)(outf + (size_t)(r + 8) * NFEAT + col) =
                    make_float2(lrelu(a[2] + b0), lrelu(a[3] + b1));
        }
}

// ---------------- global max pool ----------------
__global__ void k_pool(const float* __restrict__ h, const int* __restrict__ batch) {
    int t = threadIdx.x;
    int r0 = blockIdx.x * POOL_ROWS;
    int r1 = min(r0 + POOL_ROWS, N_NODES);
    if (r0 >= N_NODES) return;
    int curg = batch[r0];
    float m = -3.402823466e38f;
    for (int r = r0; r < r1; ++r) {
        int g = batch[r];
        if (g != curg) {
            atomicMax(&g_pool[curg * NFEAT + t], fenc(m));
            curg = g;
            m = -3.402823466e38f;
        }
        m = fmaxf(m, h[(size_t)r * NFEAT + t]);
    }
    atomicMax(&g_pool[curg * NFEAT + t], fenc(m));
}

// ---------------- final FC; re-zeroes g_pool for the next replay ----------------
__global__ void k_fc(const float* __restrict__ Wfc, const float* __restrict__ bfc,
                     float* __restrict__ out) {
    int t = threadIdx.x;
    int g = t >> 1, o = t & 1;
    float s = bfc[o];
#pragma unroll 4
    for (int k = 0; k < 128; k++) s += fdec(g_pool[g * NFEAT + k]) * Wfc[k * 2 + o];
    out[g * 2 + o] = s;
    __syncthreads();
    for (int k = t; k < NGRAPH * NFEAT; k += 128) g_pool[k] = 0u;
}

// ---------------- launch ----------------
extern "C" void kernel_launch(void* const* d_in, const int* in_sizes, int n_in,
                              void* d_out, int out_size) {
    const float* x = (const float*)d_in[0];
    const int* ei = (const int*)d_in[1];
    const int* batch = (const int*)d_in[2];
    const float* b1 = (const float*)d_in[4];
    const float* b2 = (const float*)d_in[7];
    const float* b3 = (const float*)d_in[10];
    const float* Wfc = (const float*)d_in[12];
    const float* bfc = (const float*)d_in[13];
    float* out = (float*)d_out;

    float *hf0, *hf1;
    uint4 *mh, *ml, *x0h, *x0l, *x1h, *x1l, *whi, *wlo;
    cudaGetSymbolAddress((void**)&hf0, g_hf0);
    cudaGetSymbolAddress((void**)&hf1, g_hf1);
    cudaGetSymbolAddress((void**)&mh, g_mh4);
    cudaGetSymbolAddress((void**)&ml, g_ml4);
    cudaGetSymbolAddress((void**)&x0h, g_x0h4);
    cudaGetSymbolAddress((void**)&x0l, g_x0l4);
    cudaGetSymbolAddress((void**)&x1h, g_x1h4);
    cudaGetSymbolAddress((void**)&x1l, g_x1l4);
    cudaGetSymbolAddress((void**)&whi, g_Whi4);
    cudaGetSymbolAddress((void**)&wlo, g_Wlo4);

    cudaFuncSetAttribute(k_gemm, cudaFuncAttributeMaxDynamicSharedMemorySize, GEMM_SMEM);

    const int gemm_blocks = (N_NODES + 63) / 64;           // 782
    const int agg_blocks = (N_NODES * 32 + 255) / 256;
    const int edge4_blocks = (N_EDGES / 4 + 255) / 256;    // 586
    const int LSTRIDE = 128 * 256 / 8;  // uint4 per layer

    // idx 0: fused wconv + hist (grid covers both index spaces)
    k_whist<<<edge4_blocks, 256>>>(
        (const float*)d_in[3], (const float*)d_in[5], (const float*)d_in[6],
        (const float*)d_in[8], (const float*)d_in[9], (const float*)d_in[11], ei);
    k_scan<<<1, 1024>>>();                  // idx 1 (re-zeroes g_deg)
    k_scatter<<<edge4_blocks, 256>>>(ei);   // idx 2

    // layer 1 (agg = idx 3 -> profiled slot)
    k_agg<<<agg_blocks, 256>>>(x, (uint2*)mh, (uint2*)ml, (uint2*)x0h, (uint2*)x0l);
    k_gemm<<<gemm_blocks, 256, GEMM_SMEM>>>(mh, ml, x0h, x0l, whi, wlo, b1, hf1);
    // layer 2
    k_agg<<<agg_blocks, 256>>>(hf1, (uint2*)mh, (uint2*)ml, (uint2*)x1h, (uint2*)x1l);
    k_gemm<<<gemm_blocks, 256, GEMM_SMEM>>>(mh, ml, x1h, x1l, whi + LSTRIDE,
                                            wlo + LSTRIDE, b2, hf0);
    // layer 3
    k_agg<<<agg_blocks, 256>>>(hf0, (uint2*)mh, (uint2*)ml, (uint2*)x0h, (uint2*)x0l);
    k_gemm<<<gemm_blocks, 256, GEMM_SMEM>>>(mh, ml, x0h, x0l, whi + 2 * LSTRIDE,
                                            wlo + 2 * LSTRIDE, b3, hf1);

    // pool + fc (fc re-zeroes g_pool)
    k_pool<<<(N_NODES + POOL_ROWS - 1) / POOL_ROWS, 128>>>(hf1, batch);
    k_fc<<<1, 128>>>(Wfc, bfc, out);
}

// round 10
// speedup vs baseline: 1.0739x; 1.0739x over previous
#include <cuda_runtime.h>
#include <cuda_bf16.h>
#include <cstdint>

#define N_NODES 50000
#define N_EDGES 600000
#define NFEAT 128
#define NGRAPH 64
#define POOL_ROWS 256
#define SCAN_ITEMS 49

#define GEMM_SMEM 65536  // Ah 16K | Al 16K | Bh 16K | Bl 16K

// ---------------- device scratch ----------------
__device__ int g_deg[N_NODES];               // zero-init; re-zeroed by k_scan
__device__ int g_off[N_NODES + 1];
__device__ int g_pos[N_NODES];
__device__ int g_src[N_EDGES];
__device__ unsigned g_pool[NGRAPH * NFEAT];  // zero-init; re-zeroed by k_fc
__device__ float g_hf0[(size_t)N_NODES * NFEAT];
__device__ float g_hf1[(size_t)N_NODES * NFEAT];
// bf16 hi/lo operand buffers: [node][128] bf16 = 256B/row
__device__ uint4 g_mh4[(size_t)N_NODES * NFEAT / 8];
__device__ uint4 g_ml4[(size_t)N_NODES * NFEAT / 8];
__device__ uint4 g_x0h4[(size_t)N_NODES * NFEAT / 8];
__device__ uint4 g_x0l4[(size_t)N_NODES * NFEAT / 8];
__device__ uint4 g_x1h4[(size_t)N_NODES * NFEAT / 8];
__device__ uint4 g_x1l4[(size_t)N_NODES * NFEAT / 8];
// W split: [3 layers][128 n][256 k] bf16 = 512B/row
__device__ uint4 g_Whi4[3 * 128 * 256 / 8];
__device__ uint4 g_Wlo4[3 * 128 * 256 / 8];

// ---------------- helpers ----------------
__device__ __forceinline__ float lrelu(float v) { return fmaxf(v, 0.01f * v); }
__device__ __forceinline__ unsigned fenc(float f) {
    unsigned u = __float_as_uint(f);
    return (u & 0x80000000u) ? ~u : (u | 0x80000000u);
}
__device__ __forceinline__ float fdec(unsigned u) {
    return (u & 0x80000000u) ? __uint_as_float(u & 0x7FFFFFFFu) : __uint_as_float(~u);
}
__device__ __forceinline__ uint32_t pack_hi(float a, float b) {
    __nv_bfloat162 p(__float2bfloat16_rn(a), __float2bfloat16_rn(b));
    return *reinterpret_cast<uint32_t*>(&p);
}
__device__ __forceinline__ uint32_t pack_lo(float a, float b) {
    float ra = a - __bfloat162float(__float2bfloat16_rn(a));
    float rb = b - __bfloat162float(__float2bfloat16_rn(b));
    __nv_bfloat162 p(__float2bfloat16_rn(ra), __float2bfloat16_rn(rb));
    return *reinterpret_cast<uint32_t*>(&p);
}
__device__ __forceinline__ uint32_t smem_u32(const void* p) {
    uint32_t a;
    asm("{ .reg .u64 t; cvta.to.shared.u64 t, %1; cvt.u32.u64 %0, t; }" : "=r"(a) : "l"(p));
    return a;
}
__device__ __forceinline__ void mma_bf16(float* c, const uint32_t* a, uint32_t b0,
                                         uint32_t b1) {
    asm volatile(
        "mma.sync.aligned.m16n8k16.row.col.f32.bf16.bf16.f32 "
        "{%0,%1,%2,%3}, {%4,%5,%6,%7}, {%8,%9}, {%0,%1,%2,%3};"
        : "+f"(c[0]), "+f"(c[1]), "+f"(c[2]), "+f"(c[3])
        : "r"(a[0]), "r"(a[1]), "r"(a[2]), "r"(a[3]), "r"(b0), "r"(b1));
}
__device__ __forceinline__ void ldsm4(uint32_t* r, uint32_t addr) {
    asm volatile("ldmatrix.sync.aligned.m8n8.x4.shared.b16 {%0,%1,%2,%3}, [%4];"
                 : "=r"(r[0]), "=r"(r[1]), "=r"(r[2]), "=r"(r[3]) : "r"(addr));
}
__device__ __forceinline__ void cp16(uint32_t dst, const void* src, int sz) {
    asm volatile("cp.async.ca.shared.global [%0], [%1], 16, %2;"
                 :: "r"(dst), "l"(src), "r"(sz));
}

// ---------------- fused: W pre-convert + degree histogram ----------------
__global__ void k_whist(const float* __restrict__ W1l, const float* __restrict__ W1r,
                        const float* __restrict__ W2l, const float* __restrict__ W2r,
                        const float* __restrict__ W3l, const float* __restrict__ W3r,
                        const int* __restrict__ ei) {
    int i = blockIdx.x * blockDim.x + threadIdx.x;
    if (i < 3 * 128 * 256) {
        int l = i >> 15;
        int rem = i & 32767;
        int n = rem >> 8;
        int k = rem & 255;
        const float* Wl = (l == 0) ? W1l : (l == 1) ? W2l : W3l;
        const float* Wr = (l == 0) ? W1r : (l == 1) ? W2r : W3r;
        float w = (k < 128) ? Wl[k * 128 + n] : Wr[(k - 128) * 128 + n];
        __nv_bfloat16 h = __float2bfloat16_rn(w);
        ((__nv_bfloat16*)g_Whi4)[i] = h;
        ((__nv_bfloat16*)g_Wlo4)[i] = __float2bfloat16_rn(w - __bfloat162float(h));
    }
    int e4 = i * 4;
    if (e4 < N_EDGES) {
        int4 d = *(const int4*)(ei + N_EDGES + e4);
        atomicAdd(&g_deg[d.x], 1);
        atomicAdd(&g_deg[d.y], 1);
        atomicAdd(&g_deg[d.z], 1);
        atomicAdd(&g_deg[d.w], 1);
    }
}

// single-block scan; consumes g_deg and re-zeroes it for the next replay
__global__ void k_scan() {
    __shared__ int s[1024];
    int t = threadIdx.x;
    int base = t * SCAN_ITEMS;
    int sum = 0;
    for (int j = 0; j < SCAN_ITEMS; j++) {
        int i = base + j;
        if (i < N_NODES) sum += g_deg[i];
    }
    s[t] = sum;
    for (int off = 1; off < 1024; off <<= 1) {
        __syncthreads();
        int v = (t >= off) ? s[t - off] : 0;
        __syncthreads();
        s[t] += v;
    }
    __syncthreads();
    int run = s[t] - sum;
    for (int j = 0; j < SCAN_ITEMS; j++) {
        int i = base + j;
        if (i < N_NODES) {
            int d = g_deg[i];
            g_off[i] = run;
            g_pos[i] = run;
            run += d;
            g_deg[i] = 0;
        }
    }
    if (t == 1023) g_off[N_NODES] = N_EDGES;
}

__global__ void k_scatter(const int* __restrict__ ei) {
    int e4 = (blockIdx.x * blockDim.x + threadIdx.x) * 4;
    if (e4 >= N_EDGES) return;
    int4 d = *(const int4*)(ei + N_EDGES + e4);
    int4 s = *(const int4*)(ei + e4);
    int p0 = atomicAdd(&g_pos[d.x], 1);
    int p1 = atomicAdd(&g_pos[d.y], 1);
    int p2 = atomicAdd(&g_pos[d.z], 1);
    int p3 = atomicAdd(&g_pos[d.w], 1);
    g_src[p0] = s.x;
    g_src[p1] = s.y;
    g_src[p2] = s.z;
    g_src[p3] = s.w;
}

// ---------------- mean-aggregation: one warp per node; 4-way unrolled --------------
__global__ __launch_bounds__(256) void k_agg(const float* __restrict__ in,
                                             uint2* __restrict__ mh, uint2* __restrict__ ml,
                                             uint2* __restrict__ xh, uint2* __restrict__ xl) {
    int node = (blockIdx.x * blockDim.x + threadIdx.x) >> 5;
    if (node >= N_NODES) return;
    int lane = threadIdx.x & 31;
    float4 sv = ((const float4*)(in + (size_t)node * NFEAT))[lane];
    xh[node * 32 + lane] = make_uint2(pack_hi(sv.x, sv.y), pack_hi(sv.z, sv.w));
    xl[node * 32 + lane] = make_uint2(pack_lo(sv.x, sv.y), pack_lo(sv.z, sv.w));
    int s0 = g_off[node], s1 = g_off[node + 1];
    float ax = 0.f, ay = 0.f, az = 0.f, aw = 0.f;
    int e = s0;
    for (; e + 3 < s1; e += 4) {
        int sA = g_src[e], sB = g_src[e + 1], sC = g_src[e + 2], sD = g_src[e + 3];
        float4 v0 = ((const float4*)(in + (size_t)sA * NFEAT))[lane];
        float4 v1 = ((const float4*)(in + (size_t)sB * NFEAT))[lane];
        float4 v2 = ((const float4*)(in + (size_t)sC * NFEAT))[lane];
        float4 v3 = ((const float4*)(in + (size_t)sD * NFEAT))[lane];
        ax += (v0.x + v1.x) + (v2.x + v3.x);
        ay += (v0.y + v1.y) + (v2.y + v3.y);
        az += (v0.z + v1.z) + (v2.z + v3.z);
        aw += (v0.w + v1.w) + (v2.w + v3.w);
    }
    for (; e < s1; ++e) {
        float4 v = ((const float4*)(in + (size_t)g_src[e] * NFEAT))[lane];
        ax += v.x; ay += v.y; az += v.z; aw += v.w;
    }
    float inv = 1.0f / (float)max(s1 - s0, 1);
    ax *= inv; ay *= inv; az *= inv; aw *= inv;
    mh[node * 32 + lane] = make_uint2(pack_hi(ax, ay), pack_hi(az, aw));
    ml[node * 32 + lane] = make_uint2(pack_lo(ax, ay), pack_lo(az, aw));
}

// ---------------- mma.sync dual GEMM, BM=128, split-half cp.async pipelining --------
// Tile: 128m x 128n x 256k; 4 k-chunks of 64; 8 warps = 4m x 2n (warp 32m x 64n).
// Stage (64KB): Ah@0, Al@16K, Bh@32K, Bl@48K; [128 rows][64 bf16] each, swizzled.
// Each chunk staged as two commit groups (k-halves) so ks 0-1 compute overlaps the
// second half's loads.
__global__ __launch_bounds__(256, 2) void k_gemm(
    const uint4* __restrict__ Amh, const uint4* __restrict__ Aml,
    const uint4* __restrict__ Axh, const uint4* __restrict__ Axl,
    const uint4* __restrict__ Bh, const uint4* __restrict__ Bl,
    const float* __restrict__ bias, float* __restrict__ outf) {
    extern __shared__ char smc[];
    uint32_t sb = smem_u32(smc);
    int t = threadIdx.x, lane = t & 31, wid = t >> 5;
    int qr = lane >> 2, qc = lane & 3;
    int row0 = blockIdx.x * 128;
    int wrow = (wid & 3) * 32, wcol = (wid >> 2) * 64;

    float acc[2][4][2][4];
#pragma unroll
    for (int a = 0; a < 2; a++)
#pragma unroll
        for (int b = 0; b < 4; b++)
#pragma unroll
            for (int c = 0; c < 2; c++)
#pragma unroll
                for (int d = 0; d < 4; d++) acc[a][b][c][d] = 0.f;

#define STAGE_HALF(CH, H)                                                           \
    {                                                                               \
        const int _ch = (CH);                                                       \
        const char* abh = (const char*)(_ch < 2 ? Amh : Axh);                       \
        const char* abl = (const char*)(_ch < 2 ? Aml : Axl);                       \
        int kof = (_ch & 1) * 128, bkof = _ch * 128;                                \
        for (int g = t; g < 2048; g += 256) {                                       \
            int arr = g >> 9, idx = g & 511, row = idx >> 2;                        \
            int c16 = (idx & 3) + (H) * 4;                                          \
            uint32_t dst = sb + arr * 16384 + row * 128 + ((c16 ^ (row & 7)) * 16); \
            if (arr < 2) {                                                          \
                int grow = row0 + row;                                              \
                const char* src = (arr ? abl : abh) + (size_t)grow * 256 + kof +    \
                                  c16 * 16;                                         \
                cp16(dst, src, grow < N_NODES ? 16 : 0);                            \
            } else {                                                                \
                const char* src = (arr == 2 ? (const char*)Bh : (const char*)Bl) +  \
                                  row * 512 + bkof + c16 * 16;                      \
                cp16(dst, src, 16);                                                 \
            }                                                                       \
        }                                                                           \
        asm volatile("cp.async.commit_group;");                                     \
    }

#define COMPUTE_KS(KS)                                                              \
    {                                                                               \
        const int ks = (KS);                                                        \
        uint32_t ah[2][4], al[2][4];                                                \
        _Pragma("unroll") for (int mi = 0; mi < 2; mi++) {                          \
            int row = wrow + mi * 16 + (lane & 15);                                 \
            int c16 = ks * 2 + (lane >> 4);                                         \
            uint32_t ad = sb + row * 128 + ((c16 ^ (row & 7)) * 16);                \
            ldsm4(ah[mi], ad);                                                      \
            ldsm4(al[mi], ad + 16384);                                              \
        }                                                                           \
        _Pragma("unroll") for (int ni2 = 0; ni2 < 4; ni2++) {                       \
            int row = wcol + ni2 * 16 + (lane & 7) + ((lane >> 4) << 3);            \
            int c16 = ks * 2 + ((lane >> 3) & 1);                                   \
            uint32_t bd = sb + 32768 + row * 128 + ((c16 ^ (row & 7)) * 16);        \
            uint32_t bh[4], bl[4];                                                  \
            ldsm4(bh, bd);                                                          \
            ldsm4(bl, bd + 16384);                                                  \
            _Pragma("unroll") for (int mi = 0; mi < 2; mi++) {                      \
                mma_bf16(acc[mi][ni2][0], ah[mi], bh[0], bh[1]);                    \
                mma_bf16(acc[mi][ni2][0], ah[mi], bl[0], bl[1]);                    \
                mma_bf16(acc[mi][ni2][0], al[mi], bh[0], bh[1]);                    \
                mma_bf16(acc[mi][ni2][1], ah[mi], bh[2], bh[3]);                    \
                mma_bf16(acc[mi][ni2][1], ah[mi], bl[2], bl[3]);                    \
                mma_bf16(acc[mi][ni2][1], al[mi], bh[2], bh[3]);                    \
            }                                                                       \
        }                                                                           \
    }

    for (int ch = 0; ch < 4; ch++) {
        STAGE_HALF(ch, 0);
        STAGE_HALF(ch, 1);
        asm volatile("cp.async.wait_group 1;");
        __syncthreads();
        COMPUTE_KS(0);
        COMPUTE_KS(1);
        asm volatile("cp.async.wait_group 0;");
        __syncthreads();
        COMPUTE_KS(2);
        COMPUTE_KS(3);
        __syncthreads();
    }
#undef STAGE_HALF
#undef COMPUTE_KS

    // epilogue: bias + leaky_relu, fp32
#pragma unroll
    for (int ni2 = 0; ni2 < 4; ni2++)
#pragma unroll
        for (int n8 = 0; n8 < 2; n8++) {
            int col = wcol + ni2 * 16 + n8 * 8 + qc * 2;
            float b0 = __ldg(bias + col), b1 = __ldg(bias + col + 1);
#pragma unroll
            for (int mi = 0; mi < 2; mi++) {
                float* a = acc[mi][ni2][n8];
                int r = row0 + wrow + mi * 16 + qr;
                if (r < N_NODES)
                    *(float2*)(outf + (size_t)r * NFEAT + col) =
                        make_float2(lrelu(a[0] + b0), lrelu(a[1] + b1));
                if (r + 8 < N_NODES)
                    *(float2*)(outf + (size_t)(r + 8) * NFEAT + col) =
                        make_float2(lrelu(a[2] + b0), lrelu(a[3] + b1));
            }
        }
}

// ---------------- global max pool ----------------
__global__ void k_pool(const float* __restrict__ h, const int* __restrict__ batch) {
    int t = threadIdx.x;
    int r0 = blockIdx.x * POOL_ROWS;
    int r1 = min(r0 + POOL_ROWS, N_NODES);
    if (r0 >= N_NODES) return;
    int curg = batch[r0];
    float m = -3.402823466e38f;
    for (int r = r0; r < r1; ++r) {
        int g = batch[r];
        if (g != curg) {
            atomicMax(&g_pool[curg * NFEAT + t], fenc(m));
            curg = g;
            m = -3.402823466e38f;
        }
        m = fmaxf(m, h[(size_t)r * NFEAT + t]);
    }
    atomicMax(&g_pool[curg * NFEAT + t], fenc(m));
}

// ---------------- final FC; re-zeroes g_pool for the next replay ----------------
__global__ void k_fc(const float* __restrict__ Wfc, const float* __restrict__ bfc,
                     float* __restrict__ out) {
    int t = threadIdx.x;
    int g = t >> 1, o = t & 1;
    float s = bfc[o];
#pragma unroll 4
    for (int k = 0; k < 128; k++) s += fdec(g_pool[g * NFEAT + k]) * Wfc[k * 2 + o];
    out[g * 2 + o] = s;
    __syncthreads();
    for (int k = t; k < NGRAPH * NFEAT; k += 128) g_pool[k] = 0u;
}

// ---------------- launch ----------------
extern "C" void kernel_launch(void* const* d_in, const int* in_sizes, int n_in,
                              void* d_out, int out_size) {
    const float* x = (const float*)d_in[0];
    const int* ei = (const int*)d_in[1];
    const int* batch = (const int*)d_in[2];
    const float* b1 = (const float*)d_in[4];
    const float* b2 = (const float*)d_in[7];
    const float* b3 = (const float*)d_in[10];
    const float* Wfc = (const float*)d_in[12];
    const float* bfc = (const float*)d_in[13];
    float* out = (float*)d_out;

    float *hf0, *hf1;
    uint4 *mh, *ml, *x0h, *x0l, *x1h, *x1l, *whi, *wlo;
    cudaGetSymbolAddress((void**)&hf0, g_hf0);
    cudaGetSymbolAddress((void**)&hf1, g_hf1);
    cudaGetSymbolAddress((void**)&mh, g_mh4);
    cudaGetSymbolAddress((void**)&ml, g_ml4);
    cudaGetSymbolAddress((void**)&x0h, g_x0h4);
    cudaGetSymbolAddress((void**)&x0l, g_x0l4);
    cudaGetSymbolAddress((void**)&x1h, g_x1h4);
    cudaGetSymbolAddress((void**)&x1l, g_x1l4);
    cudaGetSymbolAddress((void**)&whi, g_Whi4);
    cudaGetSymbolAddress((void**)&wlo, g_Wlo4);

    cudaFuncSetAttribute(k_gemm, cudaFuncAttributeMaxDynamicSharedMemorySize, GEMM_SMEM);

    const int gemm_blocks = (N_NODES + 127) / 128;         // 391
    const int agg_blocks = (N_NODES * 32 + 255) / 256;
    const int edge4_blocks = (N_EDGES / 4 + 255) / 256;    // 586
    const int LSTRIDE = 128 * 256 / 8;  // uint4 per layer

    k_whist<<<edge4_blocks, 256>>>(
        (const float*)d_in[3], (const float*)d_in[5], (const float*)d_in[6],
        (const float*)d_in[8], (const float*)d_in[9], (const float*)d_in[11], ei);
    k_scan<<<1, 1024>>>();
    k_scatter<<<edge4_blocks, 256>>>(ei);

    // layer 1 (agg = idx 3 -> profiled slot)
    k_agg<<<agg_blocks, 256>>>(x, (uint2*)mh, (uint2*)ml, (uint2*)x0h, (uint2*)x0l);
    k_gemm<<<gemm_blocks, 256, GEMM_SMEM>>>(mh, ml, x0h, x0l, whi, wlo, b1, hf1);
    // layer 2
    k_agg<<<agg_blocks, 256>>>(hf1, (uint2*)mh, (uint2*)ml, (uint2*)x1h, (uint2*)x1l);
    k_gemm<<<gemm_blocks, 256, GEMM_SMEM>>>(mh, ml, x1h, x1l, whi + LSTRIDE,
                                            wlo + LSTRIDE, b2, hf0);
    // layer 3
    k_agg<<<agg_blocks, 256>>>(hf0, (uint2*)mh, (uint2*)ml, (uint2*)x0h, (uint2*)x0l);
    k_gemm<<<gemm_blocks, 256, GEMM_SMEM>>>(mh, ml, x0h, x0l, whi + 2 * LSTRIDE,
                                            wlo + 2 * LSTRIDE, b3, hf1);

    // pool + fc (fc re-zeroes g_pool)
    k_pool<<<(N_NODES + POOL_ROWS - 1) / POOL_ROWS, 128>>>(hf1, batch);
    k_fc<<<1, 128>>>(Wfc, bfc, out);
}

// round 12
// speedup vs baseline: 1.0889x; 1.0139x over previous
#include <cuda_runtime.h>
#include <cuda_bf16.h>
#include <cuda_fp16.h>
#include <cstdint>

#define N_NODES 50000
#define N_EDGES 600000
#define NFEAT 128
#define NGRAPH 64
#define POOL_ROWS 256
#define SCAN_ITEMS 49

#define GEMM_SMEM 65536  // Ah 16K | Al 16K | Bh 16K | Bl 16K

// ---------------- device scratch ----------------
__device__ int g_deg[N_NODES];               // zero-init; re-zeroed by k_scan
__device__ int g_off[N_NODES + 1];
__device__ int g_pos[N_NODES];
__device__ int g_src[N_EDGES];
__device__ unsigned g_pool[NGRAPH * NFEAT];  // zero-init; re-zeroed by k_fc
// fp16 hidden-state ping/pong: [node][128] half = 256B/row (64 uint words)
__device__ unsigned g_h16a[(size_t)N_NODES * 64];
__device__ unsigned g_h16b[(size_t)N_NODES * 64];
// bf16 hi/lo operand buffers: [node][128] bf16 = 256B/row
__device__ uint4 g_mh4[(size_t)N_NODES * NFEAT / 8];
__device__ uint4 g_ml4[(size_t)N_NODES * NFEAT / 8];
__device__ uint4 g_xh4[(size_t)N_NODES * NFEAT / 8];
__device__ uint4 g_xl4[(size_t)N_NODES * NFEAT / 8];
// W split: [3 layers][128 n][256 k] bf16 = 512B/row
__device__ uint4 g_Whi4[3 * 128 * 256 / 8];
__device__ uint4 g_Wlo4[3 * 128 * 256 / 8];

// ---------------- helpers ----------------
__device__ __forceinline__ float lrelu(float v) { return fmaxf(v, 0.01f * v); }
__device__ __forceinline__ unsigned fenc(float f) {
    unsigned u = __float_as_uint(f);
    return (u & 0x80000000u) ? ~u : (u | 0x80000000u);
}
__device__ __forceinline__ float fdec(unsigned u) {
    return (u & 0x80000000u) ? __uint_as_float(u & 0x7FFFFFFFu) : __uint_as_float(~u);
}
__device__ __forceinline__ uint32_t pack_hi(float a, float b) {
    __nv_bfloat162 p(__float2bfloat16_rn(a), __float2bfloat16_rn(b));
    return *reinterpret_cast<uint32_t*>(&p);
}
__device__ __forceinline__ uint32_t pack_lo(float a, float b) {
    float ra = a - __bfloat162float(__float2bfloat16_rn(a));
    float rb = b - __bfloat162float(__float2bfloat16_rn(b));
    __nv_bfloat162 p(__float2bfloat16_rn(ra), __float2bfloat16_rn(rb));
    return *reinterpret_cast<uint32_t*>(&p);
}
__device__ __forceinline__ uint32_t smem_u32(const void* p) {
    uint32_t a;
    asm("{ .reg .u64 t; cvta.to.shared.u64 t, %1; cvt.u32.u64 %0, t; }" : "=r"(a) : "l"(p));
    return a;
}
__device__ __forceinline__ void mma_bf16(float* c, const uint32_t* a, uint32_t b0,
                                         uint32_t b1) {
    asm volatile(
        "mma.sync.aligned.m16n8k16.row.col.f32.bf16.bf16.f32 "
        "{%0,%1,%2,%3}, {%4,%5,%6,%7}, {%8,%9}, {%0,%1,%2,%3};"
        : "+f"(c[0]), "+f"(c[1]), "+f"(c[2]), "+f"(c[3])
        : "r"(a[0]), "r"(a[1]), "r"(a[2]), "r"(a[3]), "r"(b0), "r"(b1));
}
__device__ __forceinline__ void ldsm4(uint32_t* r, uint32_t addr) {
    asm volatile("ldmatrix.sync.aligned.m8n8.x4.shared.b16 {%0,%1,%2,%3}, [%4];"
                 : "=r"(r[0]), "=r"(r[1]), "=r"(r[2]), "=r"(r[3]) : "r"(addr));
}
__device__ __forceinline__ void cp16(uint32_t dst, const void* src, int sz) {
    asm volatile("cp.async.ca.shared.global [%0], [%1], 16, %2;"
                 :: "r"(dst), "l"(src), "r"(sz));
}
// unpack uint (half2) -> float2
__device__ __forceinline__ float2 h2f(unsigned u) {
    return __half22float2(*reinterpret_cast<const __half2*>(&u));
}

// ---------------- fused: W pre-convert + degree histogram ----------------
__global__ void k_whist(const float* __restrict__ W1l, const float* __restrict__ W1r,
                        const float* __restrict__ W2l, const float* __restrict__ W2r,
                        const float* __restrict__ W3l, const float* __restrict__ W3r,
                        const int* __restrict__ ei) {
    int i = blockIdx.x * blockDim.x + threadIdx.x;
    if (i < 3 * 128 * 256) {
        int l = i >> 15;
        int rem = i & 32767;
        int n = rem >> 8;
        int k = rem & 255;
        const float* Wl = (l == 0) ? W1l : (l == 1) ? W2l : W3l;
        const float* Wr = (l == 0) ? W1r : (l == 1) ? W2r : W3r;
        float w = (k < 128) ? Wl[k * 128 + n] : Wr[(k - 128) * 128 + n];
        __nv_bfloat16 h = __float2bfloat16_rn(w);
        ((__nv_bfloat16*)g_Whi4)[i] = h;
        ((__nv_bfloat16*)g_Wlo4)[i] = __float2bfloat16_rn(w - __bfloat162float(h));
    }
    int e4 = i * 4;
    if (e4 < N_EDGES) {
        int4 d = *(const int4*)(ei + N_EDGES + e4);
        atomicAdd(&g_deg[d.x], 1);
        atomicAdd(&g_deg[d.y], 1);
        atomicAdd(&g_deg[d.z], 1);
        atomicAdd(&g_deg[d.w], 1);
    }
}

// single-block scan; consumes g_deg and re-zeroes it for the next replay
__global__ void k_scan() {
    __shared__ int s[1024];
    int t = threadIdx.x;
    int base = t * SCAN_ITEMS;
    int sum = 0;
    for (int j = 0; j < SCAN_ITEMS; j++) {
        int i = base + j;
        if (i < N_NODES) sum += g_deg[i];
    }
    s[t] = sum;
    for (int off = 1; off < 1024; off <<= 1) {
        __syncthreads();
        int v = (t >= off) ? s[t - off] : 0;
        __syncthreads();
        s[t] += v;
    }
    __syncthreads();
    int run = s[t] - sum;
    for (int j = 0; j < SCAN_ITEMS; j++) {
        int i = base + j;
        if (i < N_NODES) {
            int d = g_deg[i];
            g_off[i] = run;
            g_pos[i] = run;
            run += d;
            g_deg[i] = 0;
        }
    }
    if (t == 1023) g_off[N_NODES] = N_EDGES;
}

__global__ void k_scatter(const int* __restrict__ ei) {
    int e4 = (blockIdx.x * blockDim.x + threadIdx.x) * 4;
    if (e4 >= N_EDGES) return;
    int4 d = *(const int4*)(ei + N_EDGES + e4);
    int4 s = *(const int4*)(ei + e4);
    int p0 = atomicAdd(&g_pos[d.x], 1);
    int p1 = atomicAdd(&g_pos[d.y], 1);
    int p2 = atomicAdd(&g_pos[d.z], 1);
    int p3 = atomicAdd(&g_pos[d.w], 1);
    g_src[p0] = s.x;
    g_src[p1] = s.y;
    g_src[p2] = s.z;
    g_src[p3] = s.w;
}

// ---------------- mean-aggregation, fp32 input (layer 1) ----------------
__global__ __launch_bounds__(256) void k_agg32(const float* __restrict__ in,
                                               uint2* __restrict__ mh, uint2* __restrict__ ml,
                                               uint2* __restrict__ xh, uint2* __restrict__ xl) {
    int node = (blockIdx.x * blockDim.x + threadIdx.x) >> 5;
    if (node >= N_NODES) return;
    int lane = threadIdx.x & 31;
    float4 sv = ((const float4*)(in + (size_t)node * NFEAT))[lane];
    xh[node * 32 + lane] = make_uint2(pack_hi(sv.x, sv.y), pack_hi(sv.z, sv.w));
    xl[node * 32 + lane] = make_uint2(pack_lo(sv.x, sv.y), pack_lo(sv.z, sv.w));
    int s0 = g_off[node], s1 = g_off[node + 1];
    float ax = 0.f, ay = 0.f, az = 0.f, aw = 0.f;
    int e = s0;
    for (; e + 3 < s1; e += 4) {
        int sA = g_src[e], sB = g_src[e + 1], sC = g_src[e + 2], sD = g_src[e + 3];
        float4 v0 = ((const float4*)(in + (size_t)sA * NFEAT))[lane];
        float4 v1 = ((const float4*)(in + (size_t)sB * NFEAT))[lane];
        float4 v2 = ((const float4*)(in + (size_t)sC * NFEAT))[lane];
        float4 v3 = ((const float4*)(in + (size_t)sD * NFEAT))[lane];
        ax += (v0.x + v1.x) + (v2.x + v3.x);
        ay += (v0.y + v1.y) + (v2.y + v3.y);
        az += (v0.z + v1.z) + (v2.z + v3.z);
        aw += (v0.w + v1.w) + (v2.w + v3.w);
    }
    for (; e < s1; ++e) {
        float4 v = ((const float4*)(in + (size_t)g_src[e] * NFEAT))[lane];
        ax += v.x; ay += v.y; az += v.z; aw += v.w;
    }
    float inv = 1.0f / (float)max(s1 - s0, 1);
    ax *= inv; ay *= inv; az *= inv; aw *= inv;
    mh[node * 32 + lane] = make_uint2(pack_hi(ax, ay), pack_hi(az, aw));
    ml[node * 32 + lane] = make_uint2(pack_lo(ax, ay), pack_lo(az, aw));
}

// ---------------- mean-aggregation, fp16 input (layers 2,3) ----------------
// in16: [node][64 uint] (half2 pairs); lane handles feats lane*4..lane*4+3 (uint2)
__global__ __launch_bounds__(256) void k_agg16(const unsigned* __restrict__ in16,
                                               uint2* __restrict__ mh, uint2* __restrict__ ml,
                                               uint2* __restrict__ xh, uint2* __restrict__ xl) {
    int node = (blockIdx.x * blockDim.x + threadIdx.x) >> 5;
    if (node >= N_NODES) return;
    int lane = threadIdx.x & 31;
    uint2 sp = ((const uint2*)in16)[node * 32 + lane];
    float2 s01 = h2f(sp.x), s23 = h2f(sp.y);
    xh[node * 32 + lane] = make_uint2(pack_hi(s01.x, s01.y), pack_hi(s23.x, s23.y));
    xl[node * 32 + lane] = make_uint2(pack_lo(s01.x, s01.y), pack_lo(s23.x, s23.y));
    int s0 = g_off[node], s1 = g_off[node + 1];
    float ax = 0.f, ay = 0.f, az = 0.f, aw = 0.f;
    int e = s0;
    for (; e + 3 < s1; e += 4) {
        int sA = g_src[e], sB = g_src[e + 1], sC = g_src[e + 2], sD = g_src[e + 3];
        uint2 u0 = ((const uint2*)in16)[sA * 32 + lane];
        uint2 u1 = ((const uint2*)in16)[sB * 32 + lane];
        uint2 u2 = ((const uint2*)in16)[sC * 32 + lane];
        uint2 u3 = ((const uint2*)in16)[sD * 32 + lane];
        float2 a0 = h2f(u0.x), b0 = h2f(u0.y);
        float2 a1 = h2f(u1.x), b1 = h2f(u1.y);
        float2 a2 = h2f(u2.x), b2 = h2f(u2.y);
        float2 a3 = h2f(u3.x), b3 = h2f(u3.y);
        ax += (a0.x + a1.x) + (a2.x + a3.x);
        ay += (a0.y + a1.y) + (a2.y + a3.y);
        az += (b0.x + b1.x) + (b2.x + b3.x);
        aw += (b0.y + b1.y) + (b2.y + b3.y);
    }
    for (; e < s1; ++e) {
        uint2 u = ((const uint2*)in16)[g_src[e] * 32 + lane];
        float2 a = h2f(u.x), b = h2f(u.y);
        ax += a.x; ay += a.y; az += b.x; aw += b.y;
    }
    float inv = 1.0f / (float)max(s1 - s0, 1);
    ax *= inv; ay *= inv; az *= inv; aw *= inv;
    mh[node * 32 + lane] = make_uint2(pack_hi(ax, ay), pack_hi(az, aw));
    ml[node * 32 + lane] = make_uint2(pack_lo(ax, ay), pack_lo(az, aw));
}

// ---------------- mma.sync dual GEMM (R8 config), fp16 output ----------------------
// Tile: 128m x 128n x 256k; 4 k-chunks of 64; 8 warps = 4m x 2n (warp 32m x 64n).
// smem stage (64KB): Ah@0, Al@16K, Bh@32K, Bl@48K; [128 rows][64 bf16], swizzled.
__global__ __launch_bounds__(256, 2) void k_gemm(
    const uint4* __restrict__ Amh, const uint4* __restrict__ Aml,
    const uint4* __restrict__ Axh, const uint4* __restrict__ Axl,
    const uint4* __restrict__ Bh, const uint4* __restrict__ Bl,
    const float* __restrict__ bias, unsigned* __restrict__ out16) {
    extern __shared__ char smc[];
    uint32_t sb = smem_u32(smc);
    int t = threadIdx.x, lane = t & 31, wid = t >> 5;
    int qr = lane >> 2, qc = lane & 3;
    int row0 = blockIdx.x * 128;
    int wrow = (wid & 3) * 32, wcol = (wid >> 2) * 64;

    float acc[2][4][2][4];
#pragma unroll
    for (int a = 0; a < 2; a++)
#pragma unroll
        for (int b = 0; b < 4; b++)
#pragma unroll
            for (int c = 0; c < 2; c++)
#pragma unroll
                for (int d = 0; d < 4; d++) acc[a][b][c][d] = 0.f;

#define STAGE(CH)                                                                   \
    {                                                                               \
        const int _ch = (CH);                                                       \
        const char* abh = (const char*)(_ch < 2 ? Amh : Axh);                       \
        const char* abl = (const char*)(_ch < 2 ? Aml : Axl);                       \
        int kof = (_ch & 1) * 128, bkof = _ch * 128;                                \
        for (int g = t; g < 4096; g += 256) {                                       \
            int arr = g >> 10, idx = g & 1023, row = idx >> 3, c16 = idx & 7;       \
            uint32_t dst = sb + arr * 16384 + row * 128 + ((c16 ^ (row & 7)) * 16); \
            if (arr < 2) {                                                          \
                int grow = row0 + row;                                              \
                const char* src = (arr ? abl : abh) + (size_t)grow * 256 + kof +    \
                                  c16 * 16;                                         \
                cp16(dst, src, grow < N_NODES ? 16 : 0);                            \
            } else {                                                                \
                const char* src = (arr == 2 ? (const char*)Bh : (const char*)Bl) +  \
                                  row * 512 + bkof + c16 * 16;                      \
                cp16(dst, src, 16);                                                 \
            }                                                                       \
        }                                                                           \
        asm volatile("cp.async.commit_group;");                                     \
    }

    for (int ch = 0; ch < 4; ch++) {
        STAGE(ch);
        asm volatile("cp.async.wait_group 0;");
        __syncthreads();
        uint32_t base = sb;
#pragma unroll
        for (int ks = 0; ks < 4; ks++) {
            uint32_t ah[2][4], al[2][4];
#pragma unroll
            for (int mi = 0; mi < 2; mi++) {
                int row = wrow + mi * 16 + (lane & 15);
                int c16 = ks * 2 + (lane >> 4);
                uint32_t ad = base + row * 128 + ((c16 ^ (row & 7)) * 16);
                ldsm4(ah[mi], ad);
                ldsm4(al[mi], ad + 16384);
            }
#pragma unroll
            for (int ni2 = 0; ni2 < 4; ni2++) {
                int row = wcol + ni2 * 16 + (lane & 7) + ((lane >> 4) << 3);
                int c16 = ks * 2 + ((lane >> 3) & 1);
                uint32_t bd = base + 32768 + row * 128 + ((c16 ^ (row & 7)) * 16);
                uint32_t bh[4], bl[4];
                ldsm4(bh, bd);
                ldsm4(bl, bd + 16384);
#pragma unroll
                for (int mi = 0; mi < 2; mi++) {
                    mma_bf16(acc[mi][ni2][0], ah[mi], bh[0], bh[1]);
                    mma_bf16(acc[mi][ni2][0], ah[mi], bl[0], bl[1]);
                    mma_bf16(acc[mi][ni2][0], al[mi], bh[0], bh[1]);
                    mma_bf16(acc[mi][ni2][1], ah[mi], bh[2], bh[3]);
                    mma_bf16(acc[mi][ni2][1], ah[mi], bl[2], bl[3]);
                    mma_bf16(acc[mi][ni2][1], al[mi], bh[2], bh[3]);
                }
            }
        }
        __syncthreads();
    }
#undef STAGE

    // epilogue: bias + leaky_relu, fp16 half2 stores
#pragma unroll
    for (int ni2 = 0; ni2 < 4; ni2++)
#pragma unroll
        for (int n8 = 0; n8 < 2; n8++) {
            int col = wcol + ni2 * 16 + n8 * 8 + qc * 2;
            float b0 = __ldg(bias + col), b1 = __ldg(bias + col + 1);
#pragma unroll
            for (int mi = 0; mi < 2; mi++) {
                float* a = acc[mi][ni2][n8];
                int r = row0 + wrow + mi * 16 + qr;
                if (r < N_NODES) {
                    __half2 p = __floats2half2_rn(lrelu(a[0] + b0), lrelu(a[1] + b1));
                    out16[(size_t)r * 64 + (col >> 1)] = *reinterpret_cast<unsigned*>(&p);
                }
                if (r + 8 < N_NODES) {
                    __half2 p = __floats2half2_rn(lrelu(a[2] + b0), lrelu(a[3] + b1));
                    out16[(size_t)(r + 8) * 64 + (col >> 1)] =
                        *reinterpret_cast<unsigned*>(&p);
                }
            }
        }
}

// ---------------- global max pool (fp16 input) ----------------
__global__ void k_pool(const unsigned* __restrict__ h16, const int* __restrict__ batch) {
    int t = threadIdx.x;  // column 0..127
    const __half* h = (const __half*)h16;
    int r0 = blockIdx.x * POOL_ROWS;
    int r1 = min(r0 + POOL_ROWS, N_NODES);
    if (r0 >= N_NODES) return;
    int curg = batch[r0];
    float m = -3.402823466e38f;
    for (int r = r0; r < r1; ++r) {
        int g = batch[r];
        if (g != curg) {
            atomicMax(&g_pool[curg * NFEAT + t], fenc(m));
            curg = g;
            m = -3.402823466e38f;
        }
        m = fmaxf(m, __half2float(h[(size_t)r * NFEAT + t]));
    }
    atomicMax(&g_pool[curg * NFEAT + t], fenc(m));
}

// ---------------- final FC; re-zeroes g_pool for the next replay ----------------
__global__ void k_fc(const float* __restrict__ Wfc, const float* __restrict__ bfc,
                     float* __restrict__ out) {
    int t = threadIdx.x;
    int g = t >> 1, o = t & 1;
    float s = bfc[o];
#pragma unroll 4
    for (int k = 0; k < 128; k++) s += fdec(g_pool[g * NFEAT + k]) * Wfc[k * 2 + o];
    out[g * 2 + o] = s;
    __syncthreads();
    for (int k = t; k < NGRAPH * NFEAT; k += 128) g_pool[k] = 0u;
}

// ---------------- launch ----------------
extern "C" void kernel_launch(void* const* d_in, const int* in_sizes, int n_in,
                              void* d_out, int out_size) {
    const float* x = (const float*)d_in[0];
    const int* ei = (const int*)d_in[1];
    const int* batch = (const int*)d_in[2];
    const float* b1 = (const float*)d_in[4];
    const float* b2 = (const float*)d_in[7];
    const float* b3 = (const float*)d_in[10];
    const float* Wfc = (const float*)d_in[12];
    const float* bfc = (const float*)d_in[13];
    float* out = (float*)d_out;

    unsigned *h16a, *h16b;
    uint4 *mh, *ml, *xh, *xl, *whi, *wlo;
    cudaGetSymbolAddress((void**)&h16a, g_h16a);
    cudaGetSymbolAddress((void**)&h16b, g_h16b);
    cudaGetSymbolAddress((void**)&mh, g_mh4);
    cudaGetSymbolAddress((void**)&ml, g_ml4);
    cudaGetSymbolAddress((void**)&xh, g_xh4);
    cudaGetSymbolAddress((void**)&xl, g_xl4);
    cudaGetSymbolAddress((void**)&whi, g_Whi4);
    cudaGetSymbolAddress((void**)&wlo, g_Wlo4);

    cudaFuncSetAttribute(k_gemm, cudaFuncAttributeMaxDynamicSharedMemorySize, GEMM_SMEM);

    const int gemm_blocks = (N_NODES + 127) / 128;         // 391
    const int agg_blocks = (N_NODES * 32 + 255) / 256;
    const int edge4_blocks = (N_EDGES / 4 + 255) / 256;    // 586
    const int LSTRIDE = 128 * 256 / 8;  // uint4 per layer

    k_whist<<<edge4_blocks, 256>>>(
        (const float*)d_in[3], (const float*)d_in[5], (const float*)d_in[6],
        (const float*)d_in[8], (const float*)d_in[9], (const float*)d_in[11], ei);
    k_scan<<<1, 1024>>>();
    k_scatter<<<edge4_blocks, 256>>>(ei);

    // layer 1 (fp32 x input; agg = idx 3 -> profiled slot)
    k_agg32<<<agg_blocks, 256>>>(x, (uint2*)mh, (uint2*)ml, (uint2*)xh, (uint2*)xl);
    k_gemm<<<gemm_blocks, 256, GEMM_SMEM>>>(mh, ml, xh, xl, whi, wlo, b1, h16a);
    // layer 2
    k_agg16<<<agg_blocks, 256>>>(h16a, (uint2*)mh, (uint2*)ml, (uint2*)xh, (uint2*)xl);
    k_gemm<<<gemm_blocks, 256, GEMM_SMEM>>>(mh, ml, xh, xl, whi + LSTRIDE,
                                            wlo + LSTRIDE, b2, h16b);
    // layer 3
    k_agg16<<<agg_blocks, 256>>>(h16b, (uint2*)mh, (uint2*)ml, (uint2*)xh, (uint2*)xl);
    k_gemm<<<gemm_blocks, 256, GEMM_SMEM>>>(mh, ml, xh, xl, whi + 2 * LSTRIDE,
                                            wlo + 2 * LSTRIDE, b3, h16a);

    // pool + fc (fc re-zeroes g_pool)
    k_pool<<<(N_NODES + POOL_ROWS - 1) / POOL_ROWS, 128>>>(h16a, batch);
    k_fc<<<1, 128>>>(Wfc, bfc, out);
}

// round 13
// speedup vs baseline: 1.2269x; 1.1268x over previous
#include <cuda_runtime.h>
#include <cuda_fp16.h>
#include <cstdint>

#define N_NODES 50000
#define N_EDGES 600000
#define NFEAT 128
#define NGRAPH 64
#define POOL_ROWS 256
#define SCAN_ITEMS 49

#define GEMM_SMEM 49152  // A 16K | Wh 16K | Wl 16K

// ---------------- device scratch ----------------
__device__ int g_deg[N_NODES];               // zero-init; re-zeroed by k_scan
__device__ int g_off[N_NODES + 1];
__device__ int g_pos[N_NODES];
__device__ int g_src[N_EDGES];
__device__ unsigned g_pool[NGRAPH * NFEAT];  // zero-init; re-zeroed by k_fc
// fp16 buffers: [node][128] half = 256B/row (64 uint words)
__device__ unsigned g_h16a[(size_t)N_NODES * 64];
__device__ unsigned g_h16b[(size_t)N_NODES * 64];
__device__ unsigned g_m16[(size_t)N_NODES * 64];   // mean operand
__device__ unsigned g_x16[(size_t)N_NODES * 64];   // layer-1 x operand
// W split (fp16 hi/lo): [3 layers][128 n][256 k] half = 512B/row
__device__ uint4 g_Wh4[3 * 128 * 256 / 8];
__device__ uint4 g_Wl4[3 * 128 * 256 / 8];

// ---------------- helpers ----------------
__device__ __forceinline__ float lrelu(float v) { return fmaxf(v, 0.01f * v); }
__device__ __forceinline__ unsigned fenc(float f) {
    unsigned u = __float_as_uint(f);
    return (u & 0x80000000u) ? ~u : (u | 0x80000000u);
}
__device__ __forceinline__ float fdec(unsigned u) {
    return (u & 0x80000000u) ? __uint_as_float(u & 0x7FFFFFFFu) : __uint_as_float(~u);
}
__device__ __forceinline__ unsigned packh2(float a, float b) {
    __half2 p = __floats2half2_rn(a, b);
    return *reinterpret_cast<unsigned*>(&p);
}
__device__ __forceinline__ float2 h2f(unsigned u) {
    return __half22float2(*reinterpret_cast<const __half2*>(&u));
}
__device__ __forceinline__ uint32_t smem_u32(const void* p) {
    uint32_t a;
    asm("{ .reg .u64 t; cvta.to.shared.u64 t, %1; cvt.u32.u64 %0, t; }" : "=r"(a) : "l"(p));
    return a;
}
__device__ __forceinline__ void mma_f16(float* c, const uint32_t* a, uint32_t b0,
                                        uint32_t b1) {
    asm volatile(
        "mma.sync.aligned.m16n8k16.row.col.f32.f16.f16.f32 "
        "{%0,%1,%2,%3}, {%4,%5,%6,%7}, {%8,%9}, {%0,%1,%2,%3};"
        : "+f"(c[0]), "+f"(c[1]), "+f"(c[2]), "+f"(c[3])
        : "r"(a[0]), "r"(a[1]), "r"(a[2]), "r"(a[3]), "r"(b0), "r"(b1));
}
__device__ __forceinline__ void ldsm4(uint32_t* r, uint32_t addr) {
    asm volatile("ldmatrix.sync.aligned.m8n8.x4.shared.b16 {%0,%1,%2,%3}, [%4];"
                 : "=r"(r[0]), "=r"(r[1]), "=r"(r[2]), "=r"(r[3]) : "r"(addr));
}
__device__ __forceinline__ void cp16(uint32_t dst, const void* src, int sz) {
    asm volatile("cp.async.ca.shared.global [%0], [%1], 16, %2;"
                 :: "r"(dst), "l"(src), "r"(sz));
}

// ---------------- fused: W pre-convert (fp16 hi/lo) + degree histogram -------------
__global__ void k_whist(const float* __restrict__ W1l, const float* __restrict__ W1r,
                        const float* __restrict__ W2l, const float* __restrict__ W2r,
                        const float* __restrict__ W3l, const float* __restrict__ W3r,
                        const int* __restrict__ ei) {
    int i = blockIdx.x * blockDim.x + threadIdx.x;
    if (i < 3 * 128 * 256) {
        int l = i >> 15;
        int rem = i & 32767;
        int n = rem >> 8;
        int k = rem & 255;
        const float* Wl = (l == 0) ? W1l : (l == 1) ? W2l : W3l;
        const float* Wr = (l == 0) ? W1r : (l == 1) ? W2r : W3r;
        float w = (k < 128) ? Wl[k * 128 + n] : Wr[(k - 128) * 128 + n];
        __half h = __float2half_rn(w);
        ((__half*)g_Wh4)[i] = h;
        ((__half*)g_Wl4)[i] = __float2half_rn(w - __half2float(h));
    }
    int e4 = i * 4;
    if (e4 < N_EDGES) {
        int4 d = *(const int4*)(ei + N_EDGES + e4);
        atomicAdd(&g_deg[d.x], 1);
        atomicAdd(&g_deg[d.y], 1);
        atomicAdd(&g_deg[d.z], 1);
        atomicAdd(&g_deg[d.w], 1);
    }
}

// single-block scan; consumes g_deg and re-zeroes it for the next replay
__global__ void k_scan() {
    __shared__ int s[1024];
    int t = threadIdx.x;
    int base = t * SCAN_ITEMS;
    int sum = 0;
    for (int j = 0; j < SCAN_ITEMS; j++) {
        int i = base + j;
        if (i < N_NODES) sum += g_deg[i];
    }
    s[t] = sum;
    for (int off = 1; off < 1024; off <<= 1) {
        __syncthreads();
        int v = (t >= off) ? s[t - off] : 0;
        __syncthreads();
        s[t] += v;
    }
    __syncthreads();
    int run = s[t] - sum;
    for (int j = 0; j < SCAN_ITEMS; j++) {
        int i = base + j;
        if (i < N_NODES) {
            int d = g_deg[i];
            g_off[i] = run;
            g_pos[i] = run;
            run += d;
            g_deg[i] = 0;
        }
    }
    if (t == 1023) g_off[N_NODES] = N_EDGES;
}

__global__ void k_scatter(const int* __restrict__ ei) {
    int e4 = (blockIdx.x * blockDim.x + threadIdx.x) * 4;
    if (e4 >= N_EDGES) return;
    int4 d = *(const int4*)(ei + N_EDGES + e4);
    int4 s = *(const int4*)(ei + e4);
    int p0 = atomicAdd(&g_pos[d.x], 1);
    int p1 = atomicAdd(&g_pos[d.y], 1);
    int p2 = atomicAdd(&g_pos[d.z], 1);
    int p3 = atomicAdd(&g_pos[d.w], 1);
    g_src[p0] = s.x;
    g_src[p1] = s.y;
    g_src[p2] = s.z;
    g_src[p3] = s.w;
}

// ---------------- mean-aggregation, fp32 input (layer 1): emits m16 + x16 ----------
__global__ __launch_bounds__(256) void k_agg32(const float* __restrict__ in,
                                               uint2* __restrict__ m16,
                                               uint2* __restrict__ x16) {
    int node = (blockIdx.x * blockDim.x + threadIdx.x) >> 5;
    if (node >= N_NODES) return;
    int lane = threadIdx.x & 31;
    float4 sv = ((const float4*)(in + (size_t)node * NFEAT))[lane];
    x16[node * 32 + lane] = make_uint2(packh2(sv.x, sv.y), packh2(sv.z, sv.w));
    int s0 = g_off[node], s1 = g_off[node + 1];
    float ax = 0.f, ay = 0.f, az = 0.f, aw = 0.f;
    int e = s0;
    for (; e + 3 < s1; e += 4) {
        int sA = g_src[e], sB = g_src[e + 1], sC = g_src[e + 2], sD = g_src[e + 3];
        float4 v0 = ((const float4*)(in + (size_t)sA * NFEAT))[lane];
        float4 v1 = ((const float4*)(in + (size_t)sB * NFEAT))[lane];
        float4 v2 = ((const float4*)(in + (size_t)sC * NFEAT))[lane];
        float4 v3 = ((const float4*)(in + (size_t)sD * NFEAT))[lane];
        ax += (v0.x + v1.x) + (v2.x + v3.x);
        ay += (v0.y + v1.y) + (v2.y + v3.y);
        az += (v0.z + v1.z) + (v2.z + v3.z);
        aw += (v0.w + v1.w) + (v2.w + v3.w);
    }
    for (; e < s1; ++e) {
        float4 v = ((const float4*)(in + (size_t)g_src[e] * NFEAT))[lane];
        ax += v.x; ay += v.y; az += v.z; aw += v.w;
    }
    float inv = 1.0f / (float)max(s1 - s0, 1);
    m16[node * 32 + lane] =
        make_uint2(packh2(ax * inv, ay * inv), packh2(az * inv, aw * inv));
}

// ---------------- mean-aggregation, fp16 input (layers 2,3): emits m16 only --------
__global__ __launch_bounds__(256) void k_agg16(const unsigned* __restrict__ in16,
                                               uint2* __restrict__ m16) {
    int node = (blockIdx.x * blockDim.x + threadIdx.x) >> 5;
    if (node >= N_NODES) return;
    int lane = threadIdx.x & 31;
    int s0 = g_off[node], s1 = g_off[node + 1];
    float ax = 0.f, ay = 0.f, az = 0.f, aw = 0.f;
    int e = s0;
    for (; e + 3 < s1; e += 4) {
        int sA = g_src[e], sB = g_src[e + 1], sC = g_src[e + 2], sD = g_src[e + 3];
        uint2 u0 = ((const uint2*)in16)[sA * 32 + lane];
        uint2 u1 = ((const uint2*)in16)[sB * 32 + lane];
        uint2 u2 = ((const uint2*)in16)[sC * 32 + lane];
        uint2 u3 = ((const uint2*)in16)[sD * 32 + lane];
        float2 a0 = h2f(u0.x), b0 = h2f(u0.y);
        float2 a1 = h2f(u1.x), b1 = h2f(u1.y);
        float2 a2 = h2f(u2.x), b2 = h2f(u2.y);
        float2 a3 = h2f(u3.x), b3 = h2f(u3.y);
        ax += (a0.x + a1.x) + (a2.x + a3.x);
        ay += (a0.y + a1.y) + (a2.y + a3.y);
        az += (b0.x + b1.x) + (b2.x + b3.x);
        aw += (b0.y + b1.y) + (b2.y + b3.y);
    }
    for (; e < s1; ++e) {
        uint2 u = ((const uint2*)in16)[g_src[e] * 32 + lane];
        float2 a = h2f(u.x), b = h2f(u.y);
        ax += a.x; ay += a.y; az += b.x; aw += b.y;
    }
    float inv = 1.0f / (float)max(s1 - s0, 1);
    m16[node * 32 + lane] =
        make_uint2(packh2(ax * inv, ay * inv), packh2(az * inv, aw * inv));
}

// ---------------- mma.sync dual GEMM, fp16 operands, 2-term W split -----------------
// Tile: 128m x 128n x 256k; 4 k-chunks of 64; 8 warps = 4m x 2n (warp 32m x 64n).
// smem stage (48KB): A@0 (16K), Wh@16K, Wl@32K; [128 rows][64 half = 128B], swizzled.
// Per output: D = A*(Wh + Wl), 2 mma per fragment pair (vs 3 in bf16 split).
__global__ __launch_bounds__(256, 2) void k_gemm(
    const unsigned* __restrict__ Am, const unsigned* __restrict__ Ax,
    const uint4* __restrict__ Bh, const uint4* __restrict__ Bl,
    const float* __restrict__ bias, unsigned* __restrict__ out16) {
    extern __shared__ char smc[];
    uint32_t sb = smem_u32(smc);
    int t = threadIdx.x, lane = t & 31, wid = t >> 5;
    int qr = lane >> 2, qc = lane & 3;
    int row0 = blockIdx.x * 128;
    int wrow = (wid & 3) * 32, wcol = (wid >> 2) * 64;

    float acc[2][4][2][4];
#pragma unroll
    for (int a = 0; a < 2; a++)
#pragma unroll
        for (int b = 0; b < 4; b++)
#pragma unroll
            for (int c = 0; c < 2; c++)
#pragma unroll
                for (int d = 0; d < 4; d++) acc[a][b][c][d] = 0.f;

#define STAGE(CH)                                                                   \
    {                                                                               \
        const int _ch = (CH);                                                       \
        const char* asrc = (const char*)(_ch < 2 ? Am : Ax);                        \
        int kof = (_ch & 1) * 128, bkof = _ch * 128;                                \
        for (int g = t; g < 3072; g += 256) {                                       \
            int arr = g >> 10, idx = g & 1023, row = idx >> 3, c16 = idx & 7;       \
            uint32_t dst = sb + arr * 16384 + row * 128 + ((c16 ^ (row & 7)) * 16); \
            if (arr == 0) {                                                         \
                int grow = row0 + row;                                              \
                cp16(dst, asrc + (size_t)grow * 256 + kof + c16 * 16,               \
                     grow < N_NODES ? 16 : 0);                                      \
            } else {                                                                \
                const char* src = (arr == 1 ? (const char*)Bh : (const char*)Bl) +  \
                                  row * 512 + bkof + c16 * 16;                      \
                cp16(dst, src, 16);                                                 \
            }                                                                       \
        }                                                                           \
        asm volatile("cp.async.commit_group;");                                     \
    }

    for (int ch = 0; ch < 4; ch++) {
        STAGE(ch);
        asm volatile("cp.async.wait_group 0;");
        __syncthreads();
#pragma unroll
        for (int ks = 0; ks < 4; ks++) {
            uint32_t ah[2][4];
#pragma unroll
            for (int mi = 0; mi < 2; mi++) {
                int row = wrow + mi * 16 + (lane & 15);
                int c16 = ks * 2 + (lane >> 4);
                ldsm4(ah[mi], sb + row * 128 + ((c16 ^ (row & 7)) * 16));
            }
#pragma unroll
            for (int ni2 = 0; ni2 < 4; ni2++) {
                int row = wcol + ni2 * 16 + (lane & 7) + ((lane >> 4) << 3);
                int c16 = ks * 2 + ((lane >> 3) & 1);
                uint32_t bd = sb + 16384 + row * 128 + ((c16 ^ (row & 7)) * 16);
                uint32_t bh[4], bl[4];
                ldsm4(bh, bd);
                ldsm4(bl, bd + 16384);
#pragma unroll
                for (int mi = 0; mi < 2; mi++) {
                    mma_f16(acc[mi][ni2][0], ah[mi], bh[0], bh[1]);
                    mma_f16(acc[mi][ni2][0], ah[mi], bl[0], bl[1]);
                    mma_f16(acc[mi][ni2][1], ah[mi], bh[2], bh[3]);
                    mma_f16(acc[mi][ni2][1], ah[mi], bl[2], bl[3]);
                }
            }
        }
        __syncthreads();
    }
#undef STAGE

    // epilogue: bias + leaky_relu, fp16 half2 stores
#pragma unroll
    for (int ni2 = 0; ni2 < 4; ni2++)
#pragma unroll
        for (int n8 = 0; n8 < 2; n8++) {
            int col = wcol + ni2 * 16 + n8 * 8 + qc * 2;
            float b0 = __ldg(bias + col), b1 = __ldg(bias + col + 1);
#pragma unroll
            for (int mi = 0; mi < 2; mi++) {
                float* a = acc[mi][ni2][n8];
                int r = row0 + wrow + mi * 16 + qr;
                if (r < N_NODES)
                    out16[(size_t)r * 64 + (col >> 1)] =
                        packh2(lrelu(a[0] + b0), lrelu(a[1] + b1));
                if (r + 8 < N_NODES)
                    out16[(size_t)(r + 8) * 64 + (col >> 1)] =
                        packh2(lrelu(a[2] + b0), lrelu(a[3] + b1));
            }
        }
}

// ---------------- global max pool (fp16 input) ----------------
__global__ void k_pool(const unsigned* __restrict__ h16, const int* __restrict__ batch) {
    int t = threadIdx.x;  // column 0..127
    const __half* h = (const __half*)h16;
    int r0 = blockIdx.x * POOL_ROWS;
    int r1 = min(r0 + POOL_ROWS, N_NODES);
    if (r0 >= N_NODES) return;
    int curg = batch[r0];
    float m = -3.402823466e38f;
    for (int r = r0; r < r1; ++r) {
        int g = batch[r];
        if (g != curg) {
            atomicMax(&g_pool[curg * NFEAT + t], fenc(m));
            curg = g;
            m = -3.402823466e38f;
        }
        m = fmaxf(m, __half2float(h[(size_t)r * NFEAT + t]));
    }
    atomicMax(&g_pool[curg * NFEAT + t], fenc(m));
}

// ---------------- final FC; re-zeroes g_pool for the next replay ----------------
__global__ void k_fc(const float* __restrict__ Wfc, const float* __restrict__ bfc,
                     float* __restrict__ out) {
    int t = threadIdx.x;
    int g = t >> 1, o = t & 1;
    float s = bfc[o];
#pragma unroll 4
    for (int k = 0; k < 128; k++) s += fdec(g_pool[g * NFEAT + k]) * Wfc[k * 2 + o];
    out[g * 2 + o] = s;
    __syncthreads();
    for (int k = t; k < NGRAPH * NFEAT; k += 128) g_pool[k] = 0u;
}

// ---------------- launch ----------------
extern "C" void kernel_launch(void* const* d_in, const int* in_sizes, int n_in,
                              void* d_out, int out_size) {
    const float* x = (const float*)d_in[0];
    const int* ei = (const int*)d_in[1];
    const int* batch = (const int*)d_in[2];
    const float* b1 = (const float*)d_in[4];
    const float* b2 = (const float*)d_in[7];
    const float* b3 = (const float*)d_in[10];
    const float* Wfc = (const float*)d_in[12];
    const float* bfc = (const float*)d_in[13];
    float* out = (float*)d_out;

    unsigned *h16a, *h16b, *m16, *x16;
    uint4 *wh, *wl;
    cudaGetSymbolAddress((void**)&h16a, g_h16a);
    cudaGetSymbolAddress((void**)&h16b, g_h16b);
    cudaGetSymbolAddress((void**)&m16, g_m16);
    cudaGetSymbolAddress((void**)&x16, g_x16);
    cudaGetSymbolAddress((void**)&wh, g_Wh4);
    cudaGetSymbolAddress((void**)&wl, g_Wl4);

    cudaFuncSetAttribute(k_gemm, cudaFuncAttributeMaxDynamicSharedMemorySize, GEMM_SMEM);

    const int gemm_blocks = (N_NODES + 127) / 128;         // 391
    const int agg_blocks = (N_NODES * 32 + 255) / 256;
    const int edge4_blocks = (N_EDGES / 4 + 255) / 256;    // 586
    const int LSTRIDE = 128 * 256 / 8;  // uint4 per layer

    k_whist<<<edge4_blocks, 256>>>(
        (const float*)d_in[3], (const float*)d_in[5], (const float*)d_in[6],
        (const float*)d_in[8], (const float*)d_in[9], (const float*)d_in[11], ei);
    k_scan<<<1, 1024>>>();
    k_scatter<<<edge4_blocks, 256>>>(ei);

    // layer 1 (agg32 = idx 3 -> profiled slot)
    k_agg32<<<agg_blocks, 256>>>(x, (uint2*)m16, (uint2*)x16);
    k_gemm<<<gemm_blocks, 256, GEMM_SMEM>>>(m16, x16, wh, wl, b1, h16a);
    // layer 2 (x-operand = h16a directly; exact in fp16)
    k_agg16<<<agg_blocks, 256>>>(h16a, (uint2*)m16);
    k_gemm<<<gemm_blocks, 256, GEMM_SMEM>>>(m16, h16a, wh + LSTRIDE, wl + LSTRIDE, b2,
                                            h16b);
    // layer 3
    k_agg16<<<agg_blocks, 256>>>(h16b, (uint2*)m16);
    k_gemm<<<gemm_blocks, 256, GEMM_SMEM>>>(m16, h16b, wh + 2 * LSTRIDE, wl + 2 * LSTRIDE,
                                            b3, h16a);

    // pool + fc (fc re-zeroes g_pool)
    k_pool<<<(N_NODES + POOL_ROWS - 1) / POOL_ROWS, 128>>>(h16a, batch);
    k_fc<<<1, 128>>>(Wfc, bfc, out);
}

// round 14
// speedup vs baseline: 1.3338x; 1.0871x over previous
#include <cuda_runtime.h>
#include <cuda_fp16.h>
#include <cstdint>

#define N_NODES 50000
#define N_EDGES 600000
#define NFEAT 128
#define NGRAPH 64
#define POOL_ROWS 256
#define SCAN_ITEMS 49

#define GEMM_SMEM 32768  // A 16K | W 16K

// ---------------- device scratch ----------------
__device__ int g_deg[N_NODES];               // zero-init; re-zeroed by k_scan
__device__ int g_off[N_NODES + 1];
__device__ int g_pos[N_NODES];
__device__ int g_src[N_EDGES];
__device__ unsigned g_pool[NGRAPH * NFEAT];  // zero-init; re-zeroed by k_fc
// fp16 buffers: [node][128] half = 256B/row (64 uint words)
__device__ unsigned g_h16a[(size_t)N_NODES * 64];
__device__ unsigned g_h16b[(size_t)N_NODES * 64];
__device__ unsigned g_m16[(size_t)N_NODES * 64];   // mean operand
__device__ unsigned g_x16[(size_t)N_NODES * 64];   // layer-1 x operand
// W (fp16): [3 layers][128 n][256 k] half = 512B/row
__device__ uint4 g_Wh4[3 * 128 * 256 / 8];

// ---------------- helpers ----------------
__device__ __forceinline__ float lrelu(float v) { return fmaxf(v, 0.01f * v); }
__device__ __forceinline__ unsigned fenc(float f) {
    unsigned u = __float_as_uint(f);
    return (u & 0x80000000u) ? ~u : (u | 0x80000000u);
}
__device__ __forceinline__ float fdec(unsigned u) {
    return (u & 0x80000000u) ? __uint_as_float(u & 0x7FFFFFFFu) : __uint_as_float(~u);
}
__device__ __forceinline__ unsigned packh2(float a, float b) {
    __half2 p = __floats2half2_rn(a, b);
    return *reinterpret_cast<unsigned*>(&p);
}
__device__ __forceinline__ float2 h2f(unsigned u) {
    return __half22float2(*reinterpret_cast<const __half2*>(&u));
}
__device__ __forceinline__ uint32_t smem_u32(const void* p) {
    uint32_t a;
    asm("{ .reg .u64 t; cvta.to.shared.u64 t, %1; cvt.u32.u64 %0, t; }" : "=r"(a) : "l"(p));
    return a;
}
__device__ __forceinline__ void mma_f16(float* c, const uint32_t* a, uint32_t b0,
                                        uint32_t b1) {
    asm volatile(
        "mma.sync.aligned.m16n8k16.row.col.f32.f16.f16.f32 "
        "{%0,%1,%2,%3}, {%4,%5,%6,%7}, {%8,%9}, {%0,%1,%2,%3};"
        : "+f"(c[0]), "+f"(c[1]), "+f"(c[2]), "+f"(c[3])
        : "r"(a[0]), "r"(a[1]), "r"(a[2]), "r"(a[3]), "r"(b0), "r"(b1));
}
__device__ __forceinline__ void ldsm4(uint32_t* r, uint32_t addr) {
    asm volatile("ldmatrix.sync.aligned.m8n8.x4.shared.b16 {%0,%1,%2,%3}, [%4];"
                 : "=r"(r[0]), "=r"(r[1]), "=r"(r[2]), "=r"(r[3]) : "r"(addr));
}
__device__ __forceinline__ void cp16(uint32_t dst, const void* src, int sz) {
    asm volatile("cp.async.ca.shared.global [%0], [%1], 16, %2;"
                 :: "r"(dst), "l"(src), "r"(sz));
}

// ---------------- fused: W pre-convert (fp16) + degree histogram ----------------
__global__ void k_whist(const float* __restrict__ W1l, const float* __restrict__ W1r,
                        const float* __restrict__ W2l, const float* __restrict__ W2r,
                        const float* __restrict__ W3l, const float* __restrict__ W3r,
                        const int* __restrict__ ei) {
    int i = blockIdx.x * blockDim.x + threadIdx.x;
    if (i < 3 * 128 * 256) {
        int l = i >> 15;
        int rem = i & 32767;
        int n = rem >> 8;
        int k = rem & 255;
        const float* Wl = (l == 0) ? W1l : (l == 1) ? W2l : W3l;
        const float* Wr = (l == 0) ? W1r : (l == 1) ? W2r : W3r;
        float w = (k < 128) ? Wl[k * 128 + n] : Wr[(k - 128) * 128 + n];
        ((__half*)g_Wh4)[i] = __float2half_rn(w);
    }
    int e4 = i * 4;
    if (e4 < N_EDGES) {
        int4 d = *(const int4*)(ei + N_EDGES + e4);
        atomicAdd(&g_deg[d.x], 1);
        atomicAdd(&g_deg[d.y], 1);
        atomicAdd(&g_deg[d.z], 1);
        atomicAdd(&g_deg[d.w], 1);
    }
}

// single-block scan; consumes g_deg and re-zeroes it for the next replay
__global__ void k_scan() {
    __shared__ int s[1024];
    int t = threadIdx.x;
    int base = t * SCAN_ITEMS;
    int sum = 0;
    for (int j = 0; j < SCAN_ITEMS; j++) {
        int i = base + j;
        if (i < N_NODES) sum += g_deg[i];
    }
    s[t] = sum;
    for (int off = 1; off < 1024; off <<= 1) {
        __syncthreads();
        int v = (t >= off) ? s[t - off] : 0;
        __syncthreads();
        s[t] += v;
    }
    __syncthreads();
    int run = s[t] - sum;
    for (int j = 0; j < SCAN_ITEMS; j++) {
        int i = base + j;
        if (i < N_NODES) {
            int d = g_deg[i];
            g_off[i] = run;
            g_pos[i] = run;
            run += d;
            g_deg[i] = 0;
        }
    }
    if (t == 1023) g_off[N_NODES] = N_EDGES;
}

__global__ void k_scatter(const int* __restrict__ ei) {
    int e4 = (blockIdx.x * blockDim.x + threadIdx.x) * 4;
    if (e4 >= N_EDGES) return;
    int4 d = *(const int4*)(ei + N_EDGES + e4);
    int4 s = *(const int4*)(ei + e4);
    int p0 = atomicAdd(&g_pos[d.x], 1);
    int p1 = atomicAdd(&g_pos[d.y], 1);
    int p2 = atomicAdd(&g_pos[d.z], 1);
    int p3 = atomicAdd(&g_pos[d.w], 1);
    g_src[p0] = s.x;
    g_src[p1] = s.y;
    g_src[p2] = s.z;
    g_src[p3] = s.w;
}

// ---------------- mean-aggregation, fp32 input (layer 1): emits m16 + x16 ----------
__global__ __launch_bounds__(256) void k_agg32(const float* __restrict__ in,
                                               uint2* __restrict__ m16,
                                               uint2* __restrict__ x16) {
    int node = (blockIdx.x * blockDim.x + threadIdx.x) >> 5;
    if (node >= N_NODES) return;
    int lane = threadIdx.x & 31;
    float4 sv = ((const float4*)(in + (size_t)node * NFEAT))[lane];
    x16[node * 32 + lane] = make_uint2(packh2(sv.x, sv.y), packh2(sv.z, sv.w));
    int s0 = g_off[node], s1 = g_off[node + 1];
    float ax = 0.f, ay = 0.f, az = 0.f, aw = 0.f;
    int e = s0;
    for (; e + 3 < s1; e += 4) {
        int sA = g_src[e], sB = g_src[e + 1], sC = g_src[e + 2], sD = g_src[e + 3];
        float4 v0 = ((const float4*)(in + (size_t)sA * NFEAT))[lane];
        float4 v1 = ((const float4*)(in + (size_t)sB * NFEAT))[lane];
        float4 v2 = ((const float4*)(in + (size_t)sC * NFEAT))[lane];
        float4 v3 = ((const float4*)(in + (size_t)sD * NFEAT))[lane];
        ax += (v0.x + v1.x) + (v2.x + v3.x);
        ay += (v0.y + v1.y) + (v2.y + v3.y);
        az += (v0.z + v1.z) + (v2.z + v3.z);
        aw += (v0.w + v1.w) + (v2.w + v3.w);
    }
    for (; e < s1; ++e) {
        float4 v = ((const float4*)(in + (size_t)g_src[e] * NFEAT))[lane];
        ax += v.x; ay += v.y; az += v.z; aw += v.w;
    }
    float inv = 1.0f / (float)max(s1 - s0, 1);
    m16[node * 32 + lane] =
        make_uint2(packh2(ax * inv, ay * inv), packh2(az * inv, aw * inv));
}

// ---------------- mean-aggregation, fp16 input (layers 2,3): emits m16 only --------
__global__ __launch_bounds__(256) void k_agg16(const unsigned* __restrict__ in16,
                                               uint2* __restrict__ m16) {
    int node = (blockIdx.x * blockDim.x + threadIdx.x) >> 5;
    if (node >= N_NODES) return;
    int lane = threadIdx.x & 31;
    int s0 = g_off[node], s1 = g_off[node + 1];
    float ax = 0.f, ay = 0.f, az = 0.f, aw = 0.f;
    int e = s0;
    for (; e + 3 < s1; e += 4) {
        int sA = g_src[e], sB = g_src[e + 1], sC = g_src[e + 2], sD = g_src[e + 3];
        uint2 u0 = ((const uint2*)in16)[sA * 32 + lane];
        uint2 u1 = ((const uint2*)in16)[sB * 32 + lane];
        uint2 u2 = ((const uint2*)in16)[sC * 32 + lane];
        uint2 u3 = ((const uint2*)in16)[sD * 32 + lane];
        float2 a0 = h2f(u0.x), b0 = h2f(u0.y);
        float2 a1 = h2f(u1.x), b1 = h2f(u1.y);
        float2 a2 = h2f(u2.x), b2 = h2f(u2.y);
        float2 a3 = h2f(u3.x), b3 = h2f(u3.y);
        ax += (a0.x + a1.x) + (a2.x + a3.x);
        ay += (a0.y + a1.y) + (a2.y + a3.y);
        az += (b0.x + b1.x) + (b2.x + b3.x);
        aw += (b0.y + b1.y) + (b2.y + b3.y);
    }
    for (; e < s1; ++e) {
        uint2 u = ((const uint2*)in16)[g_src[e] * 32 + lane];
        float2 a = h2f(u.x), b = h2f(u.y);
        ax += a.x; ay += a.y; az += b.x; aw += b.y;
    }
    float inv = 1.0f / (float)max(s1 - s0, 1);
    m16[node * 32 + lane] =
        make_uint2(packh2(ax * inv, ay * inv), packh2(az * inv, aw * inv));
}

// ---------------- mma.sync dual GEMM, fp16 operands, single term --------------------
// Tile: 128m x 128n x 256k; 4 k-chunks of 64; 8 warps = 4m x 2n (warp 32m x 64n).
// smem stage (32KB): A@0 (16K), W@16K; [128 rows][64 half = 128B], swizzled.
__global__ __launch_bounds__(256, 2) void k_gemm(
    const unsigned* __restrict__ Am, const unsigned* __restrict__ Ax,
    const uint4* __restrict__ Bh,
    const float* __restrict__ bias, unsigned* __restrict__ out16) {
    extern __shared__ char smc[];
    uint32_t sb = smem_u32(smc);
    int t = threadIdx.x, lane = t & 31, wid = t >> 5;
    int qr = lane >> 2, qc = lane & 3;
    int row0 = blockIdx.x * 128;
    int wrow = (wid & 3) * 32, wcol = (wid >> 2) * 64;

    float acc[2][4][2][4];
#pragma unroll
    for (int a = 0; a < 2; a++)
#pragma unroll
        for (int b = 0; b < 4; b++)
#pragma unroll
            for (int c = 0; c < 2; c++)
#pragma unroll
                for (int d = 0; d < 4; d++) acc[a][b][c][d] = 0.f;

#define STAGE(CH)                                                                   \
    {                                                                               \
        const int _ch = (CH);                                                       \
        const char* asrc = (const char*)(_ch < 2 ? Am : Ax);                        \
        int kof = (_ch & 1) * 128, bkof = _ch * 128;                                \
        for (int g = t; g < 2048; g += 256) {                                       \
            int arr = g >> 10, idx = g & 1023, row = idx >> 3, c16 = idx & 7;       \
            uint32_t dst = sb + arr * 16384 + row * 128 + ((c16 ^ (row & 7)) * 16); \
            if (arr == 0) {                                                         \
                int grow = row0 + row;                                              \
                cp16(dst, asrc + (size_t)grow * 256 + kof + c16 * 16,               \
                     grow < N_NODES ? 16 : 0);                                      \
            } else {                                                                \
                cp16(dst, (const char*)Bh + row * 512 + bkof + c16 * 16, 16);       \
            }                                                                       \
        }                                                                           \
        asm volatile("cp.async.commit_group;");                                     \
    }

    for (int ch = 0; ch < 4; ch++) {
        STAGE(ch);
        asm volatile("cp.async.wait_group 0;");
        __syncthreads();
#pragma unroll
        for (int ks = 0; ks < 4; ks++) {
            uint32_t ah[2][4];
#pragma unroll
            for (int mi = 0; mi < 2; mi++) {
                int row = wrow + mi * 16 + (lane & 15);
                int c16 = ks * 2 + (lane >> 4);
                ldsm4(ah[mi], sb + row * 128 + ((c16 ^ (row & 7)) * 16));
            }
#pragma unroll
            for (int ni2 = 0; ni2 < 4; ni2++) {
                int row = wcol + ni2 * 16 + (lane & 7) + ((lane >> 4) << 3);
                int c16 = ks * 2 + ((lane >> 3) & 1);
                uint32_t bh[4];
                ldsm4(bh, sb + 16384 + row * 128 + ((c16 ^ (row & 7)) * 16));
#pragma unroll
                for (int mi = 0; mi < 2; mi++) {
                    mma_f16(acc[mi][ni2][0], ah[mi], bh[0], bh[1]);
                    mma_f16(acc[mi][ni2][1], ah[mi], bh[2], bh[3]);
                }
            }
        }
        __syncthreads();
    }
#undef STAGE

    // epilogue: bias + leaky_relu, fp16 half2 stores
#pragma unroll
    for (int ni2 = 0; ni2 < 4; ni2++)
#pragma unroll
        for (int n8 = 0; n8 < 2; n8++) {
            int col = wcol + ni2 * 16 + n8 * 8 + qc * 2;
            float b0 = __ldg(bias + col), b1 = __ldg(bias + col + 1);
#pragma unroll
            for (int mi = 0; mi < 2; mi++) {
                float* a = acc[mi][ni2][n8];
                int r = row0 + wrow + mi * 16 + qr;
                if (r < N_NODES)
                    out16[(size_t)r * 64 + (col >> 1)] =
                        packh2(lrelu(a[0] + b0), lrelu(a[1] + b1));
                if (r + 8 < N_NODES)
                    out16[(size_t)(r + 8) * 64 + (col >> 1)] =
                        packh2(lrelu(a[2] + b0), lrelu(a[3] + b1));
            }
        }
}

// ---------------- global max pool (fp16 input) ----------------
__global__ void k_pool(const unsigned* __restrict__ h16, const int* __restrict__ batch) {
    int t = threadIdx.x;  // column 0..127
    const __half* h = (const __half*)h16;
    int r0 = blockIdx.x * POOL_ROWS;
    int r1 = min(r0 + POOL_ROWS, N_NODES);
    if (r0 >= N_NODES) return;
    int curg = batch[r0];
    float m = -3.402823466e38f;
    for (int r = r0; r < r1; ++r) {
        int g = batch[r];
        if (g != curg) {
            atomicMax(&g_pool[curg * NFEAT + t], fenc(m));
            curg = g;
            m = -3.402823466e38f;
        }
        m = fmaxf(m, __half2float(h[(size_t)r * NFEAT + t]));
    }
    atomicMax(&g_pool[curg * NFEAT + t], fenc(m));
}

// ---------------- final FC; re-zeroes g_pool for the next replay ----------------
__global__ void k_fc(const float* __restrict__ Wfc, const float* __restrict__ bfc,
                     float* __restrict__ out) {
    int t = threadIdx.x;
    int g = t >> 1, o = t & 1;
    float s = bfc[o];
#pragma unroll 4
    for (int k = 0; k < 128; k++) s += fdec(g_pool[g * NFEAT + k]) * Wfc[k * 2 + o];
    out[g * 2 + o] = s;
    __syncthreads();
    for (int k = t; k < NGRAPH * NFEAT; k += 128) g_pool[k] = 0u;
}

// ---------------- launch ----------------
extern "C" void kernel_launch(void* const* d_in, const int* in_sizes, int n_in,
                              void* d_out, int out_size) {
    const float* x = (const float*)d_in[0];
    const int* ei = (const int*)d_in[1];
    const int* batch = (const int*)d_in[2];
    const float* b1 = (const float*)d_in[4];
    const float* b2 = (const float*)d_in[7];
    const float* b3 = (const float*)d_in[10];
    const float* Wfc = (const float*)d_in[12];
    const float* bfc = (const float*)d_in[13];
    float* out = (float*)d_out;

    unsigned *h16a, *h16b, *m16, *x16;
    uint4* wh;
    cudaGetSymbolAddress((void**)&h16a, g_h16a);
    cudaGetSymbolAddress((void**)&h16b, g_h16b);
    cudaGetSymbolAddress((void**)&m16, g_m16);
    cudaGetSymbolAddress((void**)&x16, g_x16);
    cudaGetSymbolAddress((void**)&wh, g_Wh4);

    cudaFuncSetAttribute(k_gemm, cudaFuncAttributeMaxDynamicSharedMemorySize, GEMM_SMEM);

    const int gemm_blocks = (N_NODES + 127) / 128;         // 391
    const int agg_blocks = (N_NODES * 32 + 255) / 256;
    const int edge4_blocks = (N_EDGES / 4 + 255) / 256;    // 586
    const int LSTRIDE = 128 * 256 / 8;  // uint4 per layer

    k_whist<<<edge4_blocks, 256>>>(
        (const float*)d_in[3], (const float*)d_in[5], (const float*)d_in[6],
        (const float*)d_in[8], (const float*)d_in[9], (const float*)d_in[11], ei);
    k_scan<<<1, 1024>>>();
    k_scatter<<<edge4_blocks, 256>>>(ei);

    // layer 1 (agg32 = idx 3 -> profiled slot)
    k_agg32<<<agg_blocks, 256>>>(x, (uint2*)m16, (uint2*)x16);
    k_gemm<<<gemm_blocks, 256, GEMM_SMEM>>>(m16, x16, wh, b1, h16a);
    // layer 2 (x-operand = h16a directly; exact in fp16)
    k_agg16<<<agg_blocks, 256>>>(h16a, (uint2*)m16);
    k_gemm<<<gemm_blocks, 256, GEMM_SMEM>>>(m16, h16a, wh + LSTRIDE, b2, h16b);
    // layer 3
    k_agg16<<<agg_blocks, 256>>>(h16b, (uint2*)m16);
    k_gemm<<<gemm_blocks, 256, GEMM_SMEM>>>(m16, h16b, wh + 2 * LSTRIDE, b3, h16a);

    // pool + fc (fc re-zeroes g_pool)
    k_pool<<<(N_NODES + POOL_ROWS - 1) / POOL_ROWS, 128>>>(h16a, batch);
    k_fc<<<1, 128>>>(Wfc, bfc, out);
}